// round 1
// baseline (speedup 1.0000x reference)
#include <cuda_runtime.h>
#include <cuda_bf16.h>
#include <math.h>

// Problem constants: L=2048, B=4, E=1024, H=16, D=64
#define LSEQ 2048
#define BATCH 4
#define EMB 1024
#define HEADS 16
#define HDIM 64
#define MTOK (LSEQ*BATCH)      // 8192
#define NQKV (3*EMB)           // 3072

// Scratch (allocation-free: device globals). Layout [b*H+h][l][d]
__device__ float g_Q[(size_t)BATCH*HEADS*LSEQ*HDIM];
__device__ float g_K[(size_t)BATCH*HEADS*LSEQ*HDIM];
__device__ float g_V[(size_t)BATCH*HEADS*LSEQ*HDIM];
__device__ float g_ctx[(size_t)MTOK*EMB];   // [l*B+b][e] row-major

// ---------------------------------------------------------------------------
// GEMM 1: qkv = x @ W_in^T + b_in, scatter to per-head Q/K/V (Q scaled 1/8)
// C[M=8192, N=3072] ; A=x [M,1024] row-major ; B=W [N,1024] row-major (K-major)
// block tile 64x64, k-step 16, 256 threads, 4x4 per thread
// ---------------------------------------------------------------------------
__global__ __launch_bounds__(256) void qkv_gemm(const float* __restrict__ X,
                                                const float* __restrict__ W,
                                                const float* __restrict__ bias)
{
    __shared__ float As[16][68];
    __shared__ float Bs[16][68];
    const int tid = threadIdx.x;
    const int ty = tid >> 4, tx = tid & 15;
    const int m0 = blockIdx.y * 64, n0 = blockIdx.x * 64;
    const int r = tid >> 2, c4 = (tid & 3) * 4;

    const float* Arow = X + (size_t)(m0 + r) * EMB + c4;
    const float* Brow = W + (size_t)(n0 + r) * EMB + c4;

    float acc[4][4] = {};
    for (int kt = 0; kt < EMB; kt += 16) {
        float4 a = *(const float4*)(Arow + kt);
        float4 bb = *(const float4*)(Brow + kt);
        As[c4+0][r]=a.x;  As[c4+1][r]=a.y;  As[c4+2][r]=a.z;  As[c4+3][r]=a.w;
        Bs[c4+0][r]=bb.x; Bs[c4+1][r]=bb.y; Bs[c4+2][r]=bb.z; Bs[c4+3][r]=bb.w;
        __syncthreads();
        #pragma unroll
        for (int k = 0; k < 16; ++k) {
            float4 av = *(const float4*)&As[k][ty*4];
            float4 bv = *(const float4*)&Bs[k][tx*4];
            acc[0][0]+=av.x*bv.x; acc[0][1]+=av.x*bv.y; acc[0][2]+=av.x*bv.z; acc[0][3]+=av.x*bv.w;
            acc[1][0]+=av.y*bv.x; acc[1][1]+=av.y*bv.y; acc[1][2]+=av.y*bv.z; acc[1][3]+=av.y*bv.w;
            acc[2][0]+=av.z*bv.x; acc[2][1]+=av.z*bv.y; acc[2][2]+=av.z*bv.z; acc[2][3]+=av.z*bv.w;
            acc[3][0]+=av.w*bv.x; acc[3][1]+=av.w*bv.y; acc[3][2]+=av.w*bv.z; acc[3][3]+=av.w*bv.w;
        }
        __syncthreads();
    }

    // Epilogue: whole n-tile lives in one section (q/k/v) and one head.
    const int sec = n0 >> 10;                 // 0=q,1=k,2=v
    const int h   = (n0 & (EMB-1)) >> 6;      // head
    float* dst = (sec == 0) ? g_Q : (sec == 1) ? g_K : g_V;
    const float scale = (sec == 0) ? 0.125f : 1.0f;  // D^-0.5 = 1/8
    float4 bi = *(const float4*)(bias + n0 + tx*4);
    #pragma unroll
    for (int i = 0; i < 4; ++i) {
        const int t = m0 + ty*4 + i;
        const int l = t >> 2;        // t = l*B + b, B=4
        const int b = t & 3;
        float4 o;
        o.x = (acc[i][0] + bi.x) * scale;
        o.y = (acc[i][1] + bi.y) * scale;
        o.z = (acc[i][2] + bi.z) * scale;
        o.w = (acc[i][3] + bi.w) * scale;
        *(float4*)&dst[(((size_t)(b*HEADS + h) * LSEQ) + l) * HDIM + tx*4] = o;
    }
}

// ---------------------------------------------------------------------------
// Flash attention (fp32): per block = one (b,h) and 64 q-rows; 32-key tiles,
// online softmax. Writes context directly in [l*B+b][h*64+d] layout.
// ---------------------------------------------------------------------------
__global__ __launch_bounds__(256) void attn_kernel(const unsigned char* __restrict__ mask)
{
    __shared__ float Qst[64][68];   // [d][i]  (transposed)
    __shared__ float Kst[64][36];   // [d][j]  (transposed, 32 keys)
    __shared__ float Vs[32][68];    // [s][d]
    __shared__ float Ss[64][36];    // [i][s]
    __shared__ float row_m[64], row_l[64], row_alpha[64], mbias[32];

    const int tid = threadIdx.x;
    const int bh = blockIdx.y;
    const int b  = bh >> 4;
    const int h  = bh & 15;
    const int lq0 = blockIdx.x * 64;

    const float* Qp = g_Q + (size_t)bh * (LSEQ*HDIM);
    const float* Kp = g_K + (size_t)bh * (LSEQ*HDIM);
    const float* Vp = g_V + (size_t)bh * (LSEQ*HDIM);

    // Load Q tile transposed: 64 rows x 64 d
    {
        const int row = tid >> 2;
        #pragma unroll
        for (int u = 0; u < 4; ++u) {
            const int d0 = (tid & 3) * 16 + u * 4;
            float4 v = *(const float4*)(Qp + (size_t)(lq0 + row) * HDIM + d0);
            Qst[d0+0][row]=v.x; Qst[d0+1][row]=v.y; Qst[d0+2][row]=v.z; Qst[d0+3][row]=v.w;
        }
    }
    if (tid < 64) { row_m[tid] = -INFINITY; row_l[tid] = 0.0f; }

    const int ty = tid >> 4, tx = tid & 15;
    const int i0 = ty * 4;
    float o[4][4] = {};
    __syncthreads();

    for (int jt = 0; jt < LSEQ/32; ++jt) {
        const int s0 = jt * 32;
        // Load K (transposed) and V (natural) tiles: 32 x 64 each
        {
            const int row = tid >> 3;          // 0..31
            #pragma unroll
            for (int u = 0; u < 2; ++u) {
                const int d0 = (tid & 7) * 8 + u * 4;
                float4 kv = *(const float4*)(Kp + (size_t)(s0 + row) * HDIM + d0);
                Kst[d0+0][row]=kv.x; Kst[d0+1][row]=kv.y; Kst[d0+2][row]=kv.z; Kst[d0+3][row]=kv.w;
                float4 vv = *(const float4*)(Vp + (size_t)(s0 + row) * HDIM + d0);
                *(float4*)&Vs[row][d0] = vv;
            }
        }
        if (tid < 32) mbias[tid] = mask[(s0 + tid) * BATCH + b] ? -1e30f : 0.0f;
        __syncthreads();

        // S = Q K^T (64x32): thread computes rows i0..i0+3, cols j0,j0+1
        const int j0 = tx * 2;
        float s00=0,s01=0,s10=0,s11=0,s20=0,s21=0,s30=0,s31=0;
        #pragma unroll
        for (int d = 0; d < 64; ++d) {
            float4 q = *(const float4*)&Qst[d][i0];
            float2 k = *(const float2*)&Kst[d][j0];
            s00 += q.x*k.x; s01 += q.x*k.y;
            s10 += q.y*k.x; s11 += q.y*k.y;
            s20 += q.z*k.x; s21 += q.z*k.y;
            s30 += q.w*k.x; s31 += q.w*k.y;
        }
        {
            const float mb0 = mbias[j0], mb1 = mbias[j0+1];
            *(float2*)&Ss[i0+0][j0] = make_float2(s00+mb0, s01+mb1);
            *(float2*)&Ss[i0+1][j0] = make_float2(s10+mb0, s11+mb1);
            *(float2*)&Ss[i0+2][j0] = make_float2(s20+mb0, s21+mb1);
            *(float2*)&Ss[i0+3][j0] = make_float2(s30+mb0, s31+mb1);
        }
        __syncthreads();

        // Online softmax: 4 threads per row (lanes adjacent -> shfl groups)
        {
            const int row = tid >> 2, qq = tid & 3;
            float mx = -INFINITY;
            #pragma unroll
            for (int c = 0; c < 8; ++c) mx = fmaxf(mx, Ss[row][qq*8 + c]);
            mx = fmaxf(mx, __shfl_xor_sync(0xffffffffu, mx, 1));
            mx = fmaxf(mx, __shfl_xor_sync(0xffffffffu, mx, 2));
            const float m_old = row_m[row];
            const float m_new = fmaxf(m_old, mx);
            float sum = 0.0f;
            #pragma unroll
            for (int c = 0; c < 8; ++c) {
                float p = __expf(Ss[row][qq*8 + c] - m_new);
                Ss[row][qq*8 + c] = p;
                sum += p;
            }
            sum += __shfl_xor_sync(0xffffffffu, sum, 1);
            sum += __shfl_xor_sync(0xffffffffu, sum, 2);
            if (qq == 0) {
                const float alpha = __expf(m_old - m_new);
                row_alpha[row] = alpha;
                row_m[row] = m_new;
                row_l[row] = row_l[row] * alpha + sum;
            }
        }
        __syncthreads();

        // O = O*alpha + P V : thread computes rows i0..i0+3, d-cols tx*4..+3
        {
            const int tx4 = tx * 4;
            const float a0=row_alpha[i0], a1=row_alpha[i0+1], a2=row_alpha[i0+2], a3=row_alpha[i0+3];
            #pragma unroll
            for (int c = 0; c < 4; ++c) { o[0][c]*=a0; o[1][c]*=a1; o[2][c]*=a2; o[3][c]*=a3; }
            #pragma unroll
            for (int s = 0; s < 32; ++s) {
                float4 v = *(const float4*)&Vs[s][tx4];
                const float p0 = Ss[i0+0][s], p1 = Ss[i0+1][s], p2 = Ss[i0+2][s], p3 = Ss[i0+3][s];
                o[0][0]+=p0*v.x; o[0][1]+=p0*v.y; o[0][2]+=p0*v.z; o[0][3]+=p0*v.w;
                o[1][0]+=p1*v.x; o[1][1]+=p1*v.y; o[1][2]+=p1*v.z; o[1][3]+=p1*v.w;
                o[2][0]+=p2*v.x; o[2][1]+=p2*v.y; o[2][2]+=p2*v.z; o[2][3]+=p2*v.w;
                o[3][0]+=p3*v.x; o[3][1]+=p3*v.y; o[3][2]+=p3*v.z; o[3][3]+=p3*v.w;
            }
        }
        __syncthreads();
    }

    // Normalize and write context in [l*B+b][h*64+d] layout (float4)
    {
        const int tx4 = tx * 4;
        #pragma unroll
        for (int r = 0; r < 4; ++r) {
            const float inv = 1.0f / row_l[i0 + r];
            float4 ov = make_float4(o[r][0]*inv, o[r][1]*inv, o[r][2]*inv, o[r][3]*inv);
            const int l = lq0 + i0 + r;
            *(float4*)&g_ctx[((size_t)(l * BATCH + b)) * EMB + h * HDIM + tx4] = ov;
        }
    }
}

// ---------------------------------------------------------------------------
// GEMM 2: out = ctx @ W_out^T + b_out, written row-major [l*B+b][f] = d_out
// ---------------------------------------------------------------------------
__global__ __launch_bounds__(256) void out_gemm(const float* __restrict__ W,
                                                const float* __restrict__ bias,
                                                float* __restrict__ out)
{
    __shared__ float As[16][68];
    __shared__ float Bs[16][68];
    const int tid = threadIdx.x;
    const int ty = tid >> 4, tx = tid & 15;
    const int m0 = blockIdx.y * 64, n0 = blockIdx.x * 64;
    const int r = tid >> 2, c4 = (tid & 3) * 4;

    const float* Arow = g_ctx + (size_t)(m0 + r) * EMB + c4;
    const float* Brow = W + (size_t)(n0 + r) * EMB + c4;

    float acc[4][4] = {};
    for (int kt = 0; kt < EMB; kt += 16) {
        float4 a = *(const float4*)(Arow + kt);
        float4 bb = *(const float4*)(Brow + kt);
        As[c4+0][r]=a.x;  As[c4+1][r]=a.y;  As[c4+2][r]=a.z;  As[c4+3][r]=a.w;
        Bs[c4+0][r]=bb.x; Bs[c4+1][r]=bb.y; Bs[c4+2][r]=bb.z; Bs[c4+3][r]=bb.w;
        __syncthreads();
        #pragma unroll
        for (int k = 0; k < 16; ++k) {
            float4 av = *(const float4*)&As[k][ty*4];
            float4 bv = *(const float4*)&Bs[k][tx*4];
            acc[0][0]+=av.x*bv.x; acc[0][1]+=av.x*bv.y; acc[0][2]+=av.x*bv.z; acc[0][3]+=av.x*bv.w;
            acc[1][0]+=av.y*bv.x; acc[1][1]+=av.y*bv.y; acc[1][2]+=av.y*bv.z; acc[1][3]+=av.y*bv.w;
            acc[2][0]+=av.z*bv.x; acc[2][1]+=av.z*bv.y; acc[2][2]+=av.z*bv.z; acc[2][3]+=av.z*bv.w;
            acc[3][0]+=av.w*bv.x; acc[3][1]+=av.w*bv.y; acc[3][2]+=av.w*bv.z; acc[3][3]+=av.w*bv.w;
        }
        __syncthreads();
    }

    float4 bi = *(const float4*)(bias + n0 + tx*4);
    #pragma unroll
    for (int i = 0; i < 4; ++i) {
        const int t = m0 + ty*4 + i;
        float4 o;
        o.x = acc[i][0] + bi.x;
        o.y = acc[i][1] + bi.y;
        o.z = acc[i][2] + bi.z;
        o.w = acc[i][3] + bi.w;
        *(float4*)&out[(size_t)t * EMB + n0 + tx*4] = o;
    }
}

// ---------------------------------------------------------------------------
extern "C" void kernel_launch(void* const* d_in, const int* in_sizes, int n_in,
                              void* d_out, int out_size)
{
    const float* x      = (const float*)d_in[0];           // [L,B,E]
    const float* w_in   = (const float*)d_in[1];           // [3E,E]
    const float* b_in   = (const float*)d_in[2];           // [3E]
    const float* w_out  = (const float*)d_in[3];           // [E,E]
    const float* b_out  = (const float*)d_in[4];           // [E]
    const unsigned char* mask = (const unsigned char*)d_in[5]; // [L,B] bool
    float* out = (float*)d_out;                            // [L,B,E]

    qkv_gemm<<<dim3(NQKV/64, MTOK/64), 256>>>(x, w_in, b_in);
    attn_kernel<<<dim3(LSEQ/64, BATCH*HEADS), 256>>>(mask);
    out_gemm<<<dim3(EMB/64, MTOK/64), 256>>>(w_out, b_out, out);
}

// round 3
// speedup vs baseline: 3.2514x; 3.2514x over previous
#include <cuda_runtime.h>
#include <cuda_bf16.h>
#include <math.h>
#include <cstdint>

#define LSEQ 2048
#define BATCH 4
#define EMB 1024
#define HEADS 16
#define HDIM 64
#define MTOK 8192
#define NQKV 3072
#define BHN (BATCH*HEADS)

typedef __nv_bfloat16 bf16;
typedef __nv_bfloat162 bf162;

// ---------------- device scratch (allocation-free) ----------------
__device__ __align__(256) bf16 g_xh[(size_t)MTOK*EMB],  g_xl[(size_t)MTOK*EMB];
__device__ __align__(256) bf16 g_wih[(size_t)NQKV*EMB], g_wil[(size_t)NQKV*EMB];
__device__ __align__(256) bf16 g_woh[(size_t)EMB*EMB],  g_wol[(size_t)EMB*EMB];
__device__ __align__(256) bf16 g_Qh[(size_t)BHN*LSEQ*HDIM], g_Ql[(size_t)BHN*LSEQ*HDIM];
__device__ __align__(256) bf16 g_Kh[(size_t)BHN*LSEQ*HDIM], g_Kl[(size_t)BHN*LSEQ*HDIM];
__device__ __align__(256) bf16 g_Vh[(size_t)BHN*LSEQ*HDIM], g_Vl[(size_t)BHN*LSEQ*HDIM];
__device__ __align__(256) bf16 g_Vth[(size_t)BHN*HDIM*LSEQ], g_Vtl[(size_t)BHN*HDIM*LSEQ];
__device__ __align__(256) bf16 g_Ch[(size_t)MTOK*EMB], g_Cl[(size_t)MTOK*EMB];

// ---------------- helpers ----------------
__device__ __forceinline__ uint32_t smem_u32(const void* p) {
    uint32_t a;
    asm("{ .reg .u64 t; cvta.to.shared.u64 t, %1; cvt.u32.u64 %0, t; }" : "=r"(a) : "l"(p));
    return a;
}
#define CPA16(dst, src) asm volatile("cp.async.cg.shared.global [%0], [%1], 16;" :: "r"(dst), "l"(src))
#define CPCOMMIT()      asm volatile("cp.async.commit_group;")
#define CPWAIT(n)       asm volatile("cp.async.wait_group %0;" :: "n"(n))
#define LDSM4(r0,r1,r2,r3,a) \
    asm volatile("ldmatrix.sync.aligned.m8n8.x4.shared.b16 {%0,%1,%2,%3}, [%4];" \
        : "=r"(r0),"=r"(r1),"=r"(r2),"=r"(r3) : "r"(a))
#define MMA16(d,a,b) \
    asm volatile("mma.sync.aligned.m16n8k16.row.col.f32.bf16.bf16.f32 " \
        "{%0,%1,%2,%3},{%4,%5,%6,%7},{%8,%9},{%0,%1,%2,%3};" \
        : "+f"((d)[0]),"+f"((d)[1]),"+f"((d)[2]),"+f"((d)[3]) \
        : "r"((a)[0]),"r"((a)[1]),"r"((a)[2]),"r"((a)[3]),"r"((b)[0]),"r"((b)[1]))
#define SW64(o)  ((o) ^ (((o)>>3)&0x30))
#define SW128(o) ((o) ^ (((o)>>3)&0x70))

__device__ __forceinline__ void split2(float x, float y, bf162& hi, bf162& lo) {
    hi.x = __float2bfloat16_rn(x); hi.y = __float2bfloat16_rn(y);
    lo.x = __float2bfloat16_rn(x - __bfloat162float(hi.x));
    lo.y = __float2bfloat16_rn(y - __bfloat162float(hi.y));
}
__device__ __forceinline__ void packsplit(float x, float y, uint32_t& hi, uint32_t& lo) {
    bf162 h, l; split2(x, y, h, l);
    hi = *(uint32_t*)&h; lo = *(uint32_t*)&l;
}

// ---------------- projection GEMM core (C = A·B^T, 3-term bf16 split) ----------
// block 128x128, 256 thr (8 warps, 2x4), K-chunks of 32, double-buffered.
// smem stage (32KB): Ah@0, Al@8K, Bh@16K, Bl@24K; rows of 64B, SW64 swizzle.
__device__ __forceinline__ void proj_prefetch(uint32_t sbase, int ch,
    const bf16* Ah, const bf16* Al, const bf16* Bh, const bf16* Bl, int lda, int ldb)
{
    const int tid = threadIdx.x;
    const uint32_t b0 = sbase + (uint32_t)(ch & 1) * 32768u;
    #pragma unroll
    for (int it = 0; it < 8; ++it) {
        int u = it * 256 + tid;
        int op = u >> 9;
        int row = (u >> 2) & 127;
        int c = u & 3;
        const bf16* src = (op == 0) ? Ah : (op == 1) ? Al : (op == 2) ? Bh : Bl;
        int ld = (op < 2) ? lda : ldb;
        const void* s = src + (size_t)row * ld + ch * 32 + c * 8;
        uint32_t off = (uint32_t)(row * 64 + c * 16);
        CPA16(b0 + (uint32_t)op * 8192u + SW64(off), s);
    }
    CPCOMMIT();
}

__device__ __forceinline__ void proj_core(const bf16* Ah, const bf16* Al,
    const bf16* Bh, const bf16* Bl, int lda, int ldb, int nch,
    uint32_t sbase, float acc[4][4][4])
{
    const int tid = threadIdx.x, lane = tid & 31, wid = tid >> 5;
    const int wm = wid >> 2, wn = wid & 3;
    const int arow = lane & 15;
    const uint32_t acolh = (uint32_t)((lane >> 4) * 16);
    const int brow = (lane & 7) + ((lane >> 4) << 3);
    const uint32_t bcolh = (uint32_t)(((lane >> 3) & 1) * 16);

    proj_prefetch(sbase, 0, Ah, Al, Bh, Bl, lda, ldb);
    for (int ch = 0; ch < nch; ++ch) {
        if (ch + 1 < nch) { proj_prefetch(sbase, ch + 1, Ah, Al, Bh, Bl, lda, ldb); CPWAIT(1); }
        else CPWAIT(0);
        __syncthreads();
        const uint32_t b0 = sbase + (uint32_t)(ch & 1) * 32768u;
        #pragma unroll
        for (int s = 0; s < 2; ++s) {
            uint32_t ah[4][4], al[4][4], bh[4][2], bl[4][2];
            #pragma unroll
            for (int mi = 0; mi < 4; ++mi) {
                uint32_t off = (uint32_t)((wm * 64 + mi * 16 + arow) * 64 + s * 32) + acolh;
                uint32_t sw = SW64(off);
                LDSM4(ah[mi][0], ah[mi][1], ah[mi][2], ah[mi][3], b0 + sw);
                LDSM4(al[mi][0], al[mi][1], al[mi][2], al[mi][3], b0 + 8192u + sw);
            }
            #pragma unroll
            for (int p = 0; p < 2; ++p) {
                uint32_t off = (uint32_t)((wn * 32 + p * 16 + brow) * 64 + s * 32) + bcolh;
                uint32_t sw = SW64(off);
                LDSM4(bh[2*p][0], bh[2*p][1], bh[2*p+1][0], bh[2*p+1][1], b0 + 16384u + sw);
                LDSM4(bl[2*p][0], bl[2*p][1], bl[2*p+1][0], bl[2*p+1][1], b0 + 24576u + sw);
            }
            #pragma unroll
            for (int mi = 0; mi < 4; ++mi)
                #pragma unroll
                for (int ni = 0; ni < 4; ++ni) {
                    MMA16(acc[mi][ni], ah[mi], bh[ni]);
                    MMA16(acc[mi][ni], ah[mi], bl[ni]);
                    MMA16(acc[mi][ni], al[mi], bh[ni]);
                }
        }
        __syncthreads();
    }
}

// ---------------- kernels ----------------
__global__ void __launch_bounds__(256) split_fp32(const float* __restrict__ src,
                                                  bf16* __restrict__ hi,
                                                  bf16* __restrict__ lo, int n4) {
    int i = blockIdx.x * 256 + threadIdx.x;
    if (i >= n4) return;
    float4 v = ((const float4*)src)[i];
    bf162 h0, l0, h1, l1;
    split2(v.x, v.y, h0, l0);
    split2(v.z, v.w, h1, l1);
    ((bf162*)hi)[2*i] = h0; ((bf162*)hi)[2*i+1] = h1;
    ((bf162*)lo)[2*i] = l0; ((bf162*)lo)[2*i+1] = l1;
}

__global__ void __launch_bounds__(256) qkv_mma(const float* __restrict__ bias) {
    extern __shared__ char sm[];
    uint32_t sb = smem_u32(sm);
    const int m0 = blockIdx.y * 128, n0 = blockIdx.x * 128;
    float acc[4][4][4] = {};
    proj_core(g_xh + (size_t)m0 * EMB, g_xl + (size_t)m0 * EMB,
              g_wih + (size_t)n0 * EMB, g_wil + (size_t)n0 * EMB, EMB, EMB, 32, sb, acc);
    const int lane = threadIdx.x & 31, wid = threadIdx.x >> 5;
    const int wm = wid >> 2, wn = wid & 3;
    const int sec = n0 >> 10;
    bf16* dh = sec == 0 ? g_Qh : sec == 1 ? g_Kh : g_Vh;
    bf16* dl = sec == 0 ? g_Ql : sec == 1 ? g_Kl : g_Vl;
    const float scale = sec == 0 ? 0.125f : 1.0f;
    #pragma unroll
    for (int mi = 0; mi < 4; ++mi) {
        #pragma unroll
        for (int ni = 0; ni < 4; ++ni) {
            int n = n0 + wn * 32 + ni * 8 + (lane & 3) * 2;
            int h = (n & 1023) >> 6, dd = n & 63;
            float b0v = bias[n], b1v = bias[n + 1];
            #pragma unroll
            for (int half = 0; half < 2; ++half) {
                int m = m0 + wm * 64 + mi * 16 + (lane >> 2) + half * 8;
                int l = m >> 2, bb = m & 3;
                float v0 = (acc[mi][ni][half*2]     + b0v) * scale;
                float v1 = (acc[mi][ni][half*2 + 1] + b1v) * scale;
                bf162 hi, lo; split2(v0, v1, hi, lo);
                size_t off = (((size_t)(bb * HEADS + h)) * LSEQ + l) * HDIM + dd;
                *(bf162*)(dh + off) = hi; *(bf162*)(dl + off) = lo;
            }
        }
    }
}

__global__ void __launch_bounds__(256) out_mma(const float* __restrict__ bias,
                                               float* __restrict__ out) {
    extern __shared__ char sm[];
    uint32_t sb = smem_u32(sm);
    const int m0 = blockIdx.y * 128, n0 = blockIdx.x * 128;
    float acc[4][4][4] = {};
    proj_core(g_Ch + (size_t)m0 * EMB, g_Cl + (size_t)m0 * EMB,
              g_woh + (size_t)n0 * EMB, g_wol + (size_t)n0 * EMB, EMB, EMB, 32, sb, acc);
    const int lane = threadIdx.x & 31, wid = threadIdx.x >> 5;
    const int wm = wid >> 2, wn = wid & 3;
    #pragma unroll
    for (int mi = 0; mi < 4; ++mi) {
        #pragma unroll
        for (int ni = 0; ni < 4; ++ni) {
            int n = n0 + wn * 32 + ni * 8 + (lane & 3) * 2;
            float b0v = bias[n], b1v = bias[n + 1];
            #pragma unroll
            for (int half = 0; half < 2; ++half) {
                int m = m0 + wm * 64 + mi * 16 + (lane >> 2) + half * 8;
                float2 v = make_float2(acc[mi][ni][half*2] + b0v, acc[mi][ni][half*2+1] + b1v);
                *(float2*)(out + (size_t)m * EMB + n) = v;
            }
        }
    }
}

// V[bh][l][d] -> Vt[bh][d][l] (hi and lo)
__global__ void __launch_bounds__(256) transpose_v() {
    __shared__ bf16 t[64][66];
    const int bh = blockIdx.y, l0 = blockIdx.x * 64;
    #pragma unroll
    for (int a = 0; a < 2; ++a) {
        const bf16* src = (a ? g_Vl : g_Vh) + ((size_t)bh * LSEQ + l0) * HDIM;
        bf16* dst = (a ? g_Vtl : g_Vth) + (size_t)bh * HDIM * LSEQ;
        __syncthreads();
        for (int u = threadIdx.x; u < 64 * 32; u += 256) {
            int r = u >> 5, cu = u & 31;
            bf162 w = *(const bf162*)(src + (size_t)r * HDIM + cu * 2);
            t[r][cu * 2] = w.x; t[r][cu * 2 + 1] = w.y;
        }
        __syncthreads();
        for (int u = threadIdx.x; u < 64 * 32; u += 256) {
            int d = u >> 5, cl = u & 31;
            bf162 o;
            o.x = t[cl * 2][d]; o.y = t[cl * 2 + 1][d];
            *(bf162*)(dst + (size_t)d * LSEQ + l0 + cl * 2) = o;
        }
    }
}

// ---------------- fused flash attention ----------------
// smem: Qh@0 (16K), Ql@16K, stages@32K + st*32K {Kh,Kl,Vth,Vtl 8K each}, mbias@96K
__device__ __forceinline__ void attn_prefetch(uint32_t sb, int t,
    const bf16* Kh, const bf16* Kl, const bf16* Vh, const bf16* Vl)
{
    const int tid = threadIdx.x;
    const int s0 = t * 64;
    const uint32_t b0 = sb + 32768u + (uint32_t)(t & 1) * 32768u;
    #pragma unroll
    for (int it = 0; it < 8; ++it) {
        int u = it * 256 + tid;
        int op = u >> 9, idx = u & 511;
        int row = idx >> 3, c = idx & 7;
        uint32_t off = (uint32_t)(row * 128 + c * 16);
        const void* s;
        if (op == 0)      s = Kh + (size_t)(s0 + row) * HDIM + c * 8;
        else if (op == 1) s = Kl + (size_t)(s0 + row) * HDIM + c * 8;
        else if (op == 2) s = Vh + (size_t)row * LSEQ + s0 + c * 8;
        else              s = Vl + (size_t)row * LSEQ + s0 + c * 8;
        CPA16(b0 + (uint32_t)op * 8192u + SW128(off), s);
    }
    CPCOMMIT();
}

__global__ void __launch_bounds__(256) attn_mma(const unsigned char* __restrict__ mask) {
    extern __shared__ char sm[];
    uint32_t sb = smem_u32(sm);
    float* smb = (float*)(sm + 98304);
    const int tid = threadIdx.x, lane = tid & 31, wid = tid >> 5;
    const int q0 = blockIdx.x * 128, bh = blockIdx.y, b = bh >> 4, h = bh & 15;
    const bf16* Qhp = g_Qh + ((size_t)bh * LSEQ + q0) * HDIM;
    const bf16* Qlp = g_Ql + ((size_t)bh * LSEQ + q0) * HDIM;
    const bf16* Khp = g_Kh + (size_t)bh * LSEQ * HDIM;
    const bf16* Klp = g_Kl + (size_t)bh * LSEQ * HDIM;
    const bf16* Vhp = g_Vth + (size_t)bh * HDIM * LSEQ;
    const bf16* Vlp = g_Vtl + (size_t)bh * HDIM * LSEQ;

    // Q tiles + stage 0, one commit group
    #pragma unroll
    for (int it = 0; it < 8; ++it) {
        int u = it * 256 + tid;
        const bf16* src = (u < 1024) ? Qhp : Qlp;
        int idx = u & 1023;
        int row = idx >> 3, c = idx & 7;
        uint32_t off = (uint32_t)(row * 128 + c * 16);
        CPA16(sb + (u < 1024 ? 0u : 16384u) + SW128(off), src + (size_t)row * HDIM + c * 8);
    }
    attn_prefetch(sb, 0, Khp, Klp, Vhp, Vlp);

    float m0s = -1e30f, m1s = -1e30f, l0s = 0.f, l1s = 0.f;
    float o[8][4] = {};
    uint32_t qh[4][4], ql[4][4];

    const int arow = lane & 15;
    const uint32_t acolh = (uint32_t)((lane >> 4) * 16);
    const int brow = (lane & 7) + ((lane >> 4) << 3);
    const uint32_t bcolh = (uint32_t)(((lane >> 3) & 1) * 16);

    for (int t = 0; t < LSEQ / 64; ++t) {
        if (tid < 64) smb[tid] = mask[(size_t)(t * 64 + tid) * BATCH + b] ? -1e30f : 0.0f;
        if (t + 1 < LSEQ / 64) { attn_prefetch(sb, t + 1, Khp, Klp, Vhp, Vlp); CPWAIT(1); }
        else CPWAIT(0);
        __syncthreads();
        if (t == 0) {
            #pragma unroll
            for (int s = 0; s < 4; ++s) {
                uint32_t off = (uint32_t)((wid * 16 + arow) * 128 + s * 32) + acolh;
                uint32_t sw = SW128(off);
                LDSM4(qh[s][0], qh[s][1], qh[s][2], qh[s][3], sb + sw);
                LDSM4(ql[s][0], ql[s][1], ql[s][2], ql[s][3], sb + 16384u + sw);
            }
        }
        const uint32_t kb = sb + 32768u + (uint32_t)(t & 1) * 32768u;

        // S = Q K^T  (16 rows x 64 keys per warp)
        float sacc[8][4] = {};
        #pragma unroll
        for (int s = 0; s < 4; ++s) {
            uint32_t kh[8][2], kl[8][2];
            #pragma unroll
            for (int p = 0; p < 4; ++p) {
                uint32_t off = (uint32_t)((p * 16 + brow) * 128 + s * 32) + bcolh;
                uint32_t sw = SW128(off);
                LDSM4(kh[2*p][0], kh[2*p][1], kh[2*p+1][0], kh[2*p+1][1], kb + sw);
                LDSM4(kl[2*p][0], kl[2*p][1], kl[2*p+1][0], kl[2*p+1][1], kb + 8192u + sw);
            }
            #pragma unroll
            for (int ni = 0; ni < 8; ++ni) {
                MMA16(sacc[ni], qh[s], kh[ni]);
                MMA16(sacc[ni], qh[s], kl[ni]);
                MMA16(sacc[ni], ql[s], kh[ni]);
            }
        }

        // mask + online softmax (rows r0 = lane>>2, r0+8)
        float mx0 = -1e30f, mx1 = -1e30f;
        #pragma unroll
        for (int ni = 0; ni < 8; ++ni) {
            float mb0 = smb[ni * 8 + (lane & 3) * 2];
            float mb1 = smb[ni * 8 + (lane & 3) * 2 + 1];
            sacc[ni][0] += mb0; sacc[ni][1] += mb1;
            sacc[ni][2] += mb0; sacc[ni][3] += mb1;
            mx0 = fmaxf(mx0, fmaxf(sacc[ni][0], sacc[ni][1]));
            mx1 = fmaxf(mx1, fmaxf(sacc[ni][2], sacc[ni][3]));
        }
        mx0 = fmaxf(mx0, __shfl_xor_sync(0xffffffffu, mx0, 1));
        mx0 = fmaxf(mx0, __shfl_xor_sync(0xffffffffu, mx0, 2));
        mx1 = fmaxf(mx1, __shfl_xor_sync(0xffffffffu, mx1, 1));
        mx1 = fmaxf(mx1, __shfl_xor_sync(0xffffffffu, mx1, 2));
        float mn0 = fmaxf(m0s, mx0), mn1 = fmaxf(m1s, mx1);
        float al0 = __expf(m0s - mn0), al1 = __expf(m1s - mn1);
        float su0 = 0.f, su1 = 0.f;
        #pragma unroll
        for (int ni = 0; ni < 8; ++ni) {
            sacc[ni][0] = __expf(sacc[ni][0] - mn0);
            sacc[ni][1] = __expf(sacc[ni][1] - mn0);
            sacc[ni][2] = __expf(sacc[ni][2] - mn1);
            sacc[ni][3] = __expf(sacc[ni][3] - mn1);
            su0 += sacc[ni][0] + sacc[ni][1];
            su1 += sacc[ni][2] + sacc[ni][3];
        }
        su0 += __shfl_xor_sync(0xffffffffu, su0, 1);
        su0 += __shfl_xor_sync(0xffffffffu, su0, 2);
        su1 += __shfl_xor_sync(0xffffffffu, su1, 1);
        su1 += __shfl_xor_sync(0xffffffffu, su1, 2);
        m0s = mn0; m1s = mn1;
        l0s = l0s * al0 + su0; l1s = l1s * al1 + su1;
        #pragma unroll
        for (int di = 0; di < 8; ++di) {
            o[di][0] *= al0; o[di][1] *= al0;
            o[di][2] *= al1; o[di][3] *= al1;
        }

        // O += P V  (P from sacc via C->A frag identity, split hi/lo)
        #pragma unroll
        for (int s = 0; s < 4; ++s) {
            uint32_t ph[4], pl[4];
            packsplit(sacc[2*s][0],   sacc[2*s][1],   ph[0], pl[0]);
            packsplit(sacc[2*s][2],   sacc[2*s][3],   ph[1], pl[1]);
            packsplit(sacc[2*s+1][0], sacc[2*s+1][1], ph[2], pl[2]);
            packsplit(sacc[2*s+1][2], sacc[2*s+1][3], ph[3], pl[3]);
            uint32_t vh[8][2], vl[8][2];
            #pragma unroll
            for (int p = 0; p < 4; ++p) {
                uint32_t off = (uint32_t)((p * 16 + brow) * 128 + s * 32) + bcolh;
                uint32_t sw = SW128(off);
                LDSM4(vh[2*p][0], vh[2*p][1], vh[2*p+1][0], vh[2*p+1][1], kb + 16384u + sw);
                LDSM4(vl[2*p][0], vl[2*p][1], vl[2*p+1][0], vl[2*p+1][1], kb + 24576u + sw);
            }
            #pragma unroll
            for (int di = 0; di < 8; ++di) {
                MMA16(o[di], ph, vh[di]);
                MMA16(o[di], pl, vh[di]);
                MMA16(o[di], ph, vl[di]);
            }
        }
        __syncthreads();
    }

    // normalize + write ctx (hi/lo split, token-major)
    float inv0 = 1.f / l0s, inv1 = 1.f / l1s;
    int r0 = q0 + wid * 16 + (lane >> 2);
    #pragma unroll
    for (int di = 0; di < 8; ++di) {
        int col = h * 64 + di * 8 + (lane & 3) * 2;
        bf162 hi, lo;
        split2(o[di][0] * inv0, o[di][1] * inv0, hi, lo);
        size_t off0 = (size_t)(r0 * BATCH + b) * EMB + col;
        *(bf162*)(g_Ch + off0) = hi; *(bf162*)(g_Cl + off0) = lo;
        split2(o[di][2] * inv1, o[di][3] * inv1, hi, lo);
        size_t off1 = (size_t)((r0 + 8) * BATCH + b) * EMB + col;
        *(bf162*)(g_Ch + off1) = hi; *(bf162*)(g_Cl + off1) = lo;
    }
}

// ---------------- launch ----------------
extern "C" void kernel_launch(void* const* d_in, const int* in_sizes, int n_in,
                              void* d_out, int out_size)
{
    const float* x     = (const float*)d_in[0];
    const float* w_in  = (const float*)d_in[1];
    const float* b_in  = (const float*)d_in[2];
    const float* w_out = (const float*)d_in[3];
    const float* b_out = (const float*)d_in[4];
    const unsigned char* mask = (const unsigned char*)d_in[5];
    float* out = (float*)d_out;

    constexpr int SMEM_PROJ = 65536;
    constexpr int SMEM_ATTN = 98304 + 256;
    cudaFuncSetAttribute(qkv_mma,  cudaFuncAttributeMaxDynamicSharedMemorySize, SMEM_PROJ);
    cudaFuncSetAttribute(out_mma,  cudaFuncAttributeMaxDynamicSharedMemorySize, SMEM_PROJ);
    cudaFuncSetAttribute(attn_mma, cudaFuncAttributeMaxDynamicSharedMemorySize, SMEM_ATTN);

    bf16 *xh, *xl, *wih, *wil, *woh, *wol;
    cudaGetSymbolAddress((void**)&xh,  g_xh);  cudaGetSymbolAddress((void**)&xl,  g_xl);
    cudaGetSymbolAddress((void**)&wih, g_wih); cudaGetSymbolAddress((void**)&wil, g_wil);
    cudaGetSymbolAddress((void**)&woh, g_woh); cudaGetSymbolAddress((void**)&wol, g_wol);

    split_fp32<<<(MTOK*EMB/4 + 255)/256, 256>>>(x,     xh,  xl,  MTOK*EMB/4);
    split_fp32<<<(NQKV*EMB/4 + 255)/256, 256>>>(w_in,  wih, wil, NQKV*EMB/4);
    split_fp32<<<(EMB*EMB/4  + 255)/256, 256>>>(w_out, woh, wol, EMB*EMB/4);

    qkv_mma<<<dim3(NQKV/128, MTOK/128), 256, SMEM_PROJ>>>(b_in);
    transpose_v<<<dim3(LSEQ/64, BHN), 256>>>();
    attn_mma<<<dim3(LSEQ/128, BHN), 256, SMEM_ATTN>>>(mask);
    out_mma<<<dim3(EMB/128, MTOK/128), 256, SMEM_PROJ>>>(b_out, out);
}

// round 4
// speedup vs baseline: 3.3075x; 1.0172x over previous
#include <cuda_runtime.h>
#include <cuda_bf16.h>
#include <math.h>
#include <cstdint>

#define LSEQ 2048
#define BATCH 4
#define EMB 1024
#define HEADS 16
#define HDIM 64
#define MTOK 8192
#define NQKV 3072
#define BHN (BATCH*HEADS)

typedef __nv_bfloat16 bf16;
typedef __nv_bfloat162 bf162;

// ---------------- device scratch (allocation-free) ----------------
__device__ __align__(256) bf16 g_xh[(size_t)MTOK*EMB],  g_xl[(size_t)MTOK*EMB];
__device__ __align__(256) bf16 g_wih[(size_t)NQKV*EMB], g_wil[(size_t)NQKV*EMB];
__device__ __align__(256) bf16 g_woh[(size_t)EMB*EMB],  g_wol[(size_t)EMB*EMB];
__device__ __align__(256) bf16 g_Qh[(size_t)BHN*LSEQ*HDIM], g_Ql[(size_t)BHN*LSEQ*HDIM];
__device__ __align__(256) bf16 g_Kh[(size_t)BHN*LSEQ*HDIM], g_Kl[(size_t)BHN*LSEQ*HDIM];
__device__ __align__(256) bf16 g_Vh[(size_t)BHN*LSEQ*HDIM], g_Vl[(size_t)BHN*LSEQ*HDIM];
__device__ __align__(256) bf16 g_Vth[(size_t)BHN*HDIM*LSEQ], g_Vtl[(size_t)BHN*HDIM*LSEQ];
__device__ __align__(256) bf16 g_Ch[(size_t)MTOK*EMB], g_Cl[(size_t)MTOK*EMB];

// ---------------- helpers ----------------
__device__ __forceinline__ uint32_t smem_u32(const void* p) {
    uint32_t a;
    asm("{ .reg .u64 t; cvta.to.shared.u64 t, %1; cvt.u32.u64 %0, t; }" : "=r"(a) : "l"(p));
    return a;
}
#define CPA16(dst, src) asm volatile("cp.async.cg.shared.global [%0], [%1], 16;" :: "r"(dst), "l"(src))
#define CPCOMMIT()      asm volatile("cp.async.commit_group;")
#define CPWAIT(n)       asm volatile("cp.async.wait_group %0;" :: "n"(n))
#define LDSM4(r0,r1,r2,r3,a) \
    asm volatile("ldmatrix.sync.aligned.m8n8.x4.shared.b16 {%0,%1,%2,%3}, [%4];" \
        : "=r"(r0),"=r"(r1),"=r"(r2),"=r"(r3) : "r"(a))
#define MMA16(d,a,b) \
    asm volatile("mma.sync.aligned.m16n8k16.row.col.f32.bf16.bf16.f32 " \
        "{%0,%1,%2,%3},{%4,%5,%6,%7},{%8,%9},{%0,%1,%2,%3};" \
        : "+f"((d)[0]),"+f"((d)[1]),"+f"((d)[2]),"+f"((d)[3]) \
        : "r"((a)[0]),"r"((a)[1]),"r"((a)[2]),"r"((a)[3]),"r"((b)[0]),"r"((b)[1]))
#define SW64(o)  ((o) ^ (((o)>>3)&0x30))
#define SW128(o) ((o) ^ (((o)>>3)&0x70))

__device__ __forceinline__ void split2(float x, float y, bf162& hi, bf162& lo) {
    hi.x = __float2bfloat16_rn(x); hi.y = __float2bfloat16_rn(y);
    lo.x = __float2bfloat16_rn(x - __bfloat162float(hi.x));
    lo.y = __float2bfloat16_rn(y - __bfloat162float(hi.y));
}
__device__ __forceinline__ void packsplit(float x, float y, uint32_t& hi, uint32_t& lo) {
    bf162 h, l; split2(x, y, h, l);
    hi = *(uint32_t*)&h; lo = *(uint32_t*)&l;
}

// ---------------- projection GEMM core (C = A·B^T, 3-term bf16 split) ----------
// block 128x128, 256 thr (8 warps, 2x4), K-chunks of 32, 3-stage cp.async ring.
// stage (32KB): Ah@0, Al@8K, Bh@16K, Bl@24K; rows of 64B, SW64 swizzle.
__device__ __forceinline__ void proj_prefetch(uint32_t sbase, int ch,
    const bf16* Ah, const bf16* Al, const bf16* Bh, const bf16* Bl, int lda, int ldb)
{
    const int tid = threadIdx.x;
    const uint32_t b0 = sbase + (uint32_t)(ch % 3) * 32768u;
    #pragma unroll
    for (int it = 0; it < 8; ++it) {
        int u = it * 256 + tid;
        int op = u >> 9;
        int row = (u >> 2) & 127;
        int c = u & 3;
        const bf16* src = (op == 0) ? Ah : (op == 1) ? Al : (op == 2) ? Bh : Bl;
        int ld = (op < 2) ? lda : ldb;
        const void* s = src + (size_t)row * ld + ch * 32 + c * 8;
        uint32_t off = (uint32_t)(row * 64 + c * 16);
        CPA16(b0 + (uint32_t)op * 8192u + SW64(off), s);
    }
    CPCOMMIT();
}

__device__ __forceinline__ void proj_core(const bf16* Ah, const bf16* Al,
    const bf16* Bh, const bf16* Bl, int lda, int ldb, int nch,
    uint32_t sbase, float acc[4][4][4])
{
    const int tid = threadIdx.x, lane = tid & 31, wid = tid >> 5;
    const int wm = wid >> 2, wn = wid & 3;
    const int arow = lane & 15;
    const uint32_t acolh = (uint32_t)((lane >> 4) * 16);
    const int brow = (lane & 7) + ((lane >> 4) << 3);
    const uint32_t bcolh = (uint32_t)(((lane >> 3) & 1) * 16);

    proj_prefetch(sbase, 0, Ah, Al, Bh, Bl, lda, ldb);
    proj_prefetch(sbase, 1, Ah, Al, Bh, Bl, lda, ldb);
    for (int ch = 0; ch < nch; ++ch) {
        if (ch + 1 < nch) CPWAIT(1); else CPWAIT(0);
        __syncthreads();
        if (ch + 2 < nch) proj_prefetch(sbase, ch + 2, Ah, Al, Bh, Bl, lda, ldb);
        const uint32_t b0 = sbase + (uint32_t)(ch % 3) * 32768u;
        #pragma unroll
        for (int s = 0; s < 2; ++s) {
            uint32_t ah[4][4], al[4][4], bh[4][2], bl[4][2];
            #pragma unroll
            for (int mi = 0; mi < 4; ++mi) {
                uint32_t off = (uint32_t)((wm * 64 + mi * 16 + arow) * 64 + s * 32) + acolh;
                uint32_t sw = SW64(off);
                LDSM4(ah[mi][0], ah[mi][1], ah[mi][2], ah[mi][3], b0 + sw);
                LDSM4(al[mi][0], al[mi][1], al[mi][2], al[mi][3], b0 + 8192u + sw);
            }
            #pragma unroll
            for (int p = 0; p < 2; ++p) {
                uint32_t off = (uint32_t)((wn * 32 + p * 16 + brow) * 64 + s * 32) + bcolh;
                uint32_t sw = SW64(off);
                LDSM4(bh[2*p][0], bh[2*p][1], bh[2*p+1][0], bh[2*p+1][1], b0 + 16384u + sw);
                LDSM4(bl[2*p][0], bl[2*p][1], bl[2*p+1][0], bl[2*p+1][1], b0 + 24576u + sw);
            }
            #pragma unroll
            for (int mi = 0; mi < 4; ++mi)
                #pragma unroll
                for (int ni = 0; ni < 4; ++ni) {
                    MMA16(acc[mi][ni], ah[mi], bh[ni]);
                    MMA16(acc[mi][ni], ah[mi], bl[ni]);
                    MMA16(acc[mi][ni], al[mi], bh[ni]);
                }
        }
    }
}

// ---------------- kernels ----------------
__global__ void __launch_bounds__(256) split_fp32(const float* __restrict__ src,
                                                  bf16* __restrict__ hi,
                                                  bf16* __restrict__ lo, int n4) {
    int i = blockIdx.x * 256 + threadIdx.x;
    if (i >= n4) return;
    float4 v = ((const float4*)src)[i];
    bf162 h0, l0, h1, l1;
    split2(v.x, v.y, h0, l0);
    split2(v.z, v.w, h1, l1);
    ((bf162*)hi)[2*i] = h0; ((bf162*)hi)[2*i+1] = h1;
    ((bf162*)lo)[2*i] = l0; ((bf162*)lo)[2*i+1] = l1;
}

__global__ void __launch_bounds__(256) qkv_mma(const float* __restrict__ bias) {
    extern __shared__ char sm[];
    uint32_t sb = smem_u32(sm);
    const int m0 = blockIdx.y * 128, n0 = blockIdx.x * 128;
    float acc[4][4][4] = {};
    proj_core(g_xh + (size_t)m0 * EMB, g_xl + (size_t)m0 * EMB,
              g_wih + (size_t)n0 * EMB, g_wil + (size_t)n0 * EMB, EMB, EMB, 32, sb, acc);
    const int lane = threadIdx.x & 31, wid = threadIdx.x >> 5;
    const int wm = wid >> 2, wn = wid & 3;
    const int sec = n0 >> 10;
    bf16* dh = sec == 0 ? g_Qh : sec == 1 ? g_Kh : g_Vh;
    bf16* dl = sec == 0 ? g_Ql : sec == 1 ? g_Kl : g_Vl;
    const float scale = sec == 0 ? 0.125f : 1.0f;
    #pragma unroll
    for (int mi = 0; mi < 4; ++mi) {
        #pragma unroll
        for (int ni = 0; ni < 4; ++ni) {
            int n = n0 + wn * 32 + ni * 8 + (lane & 3) * 2;
            int h = (n & 1023) >> 6, dd = n & 63;
            float b0v = bias[n], b1v = bias[n + 1];
            #pragma unroll
            for (int half = 0; half < 2; ++half) {
                int m = m0 + wm * 64 + mi * 16 + (lane >> 2) + half * 8;
                int l = m >> 2, bb = m & 3;
                float v0 = (acc[mi][ni][half*2]     + b0v) * scale;
                float v1 = (acc[mi][ni][half*2 + 1] + b1v) * scale;
                bf162 hi, lo; split2(v0, v1, hi, lo);
                size_t off = (((size_t)(bb * HEADS + h)) * LSEQ + l) * HDIM + dd;
                *(bf162*)(dh + off) = hi; *(bf162*)(dl + off) = lo;
            }
        }
    }
}

__global__ void __launch_bounds__(256) out_mma(const float* __restrict__ bias,
                                               float* __restrict__ out) {
    extern __shared__ char sm[];
    uint32_t sb = smem_u32(sm);
    const int m0 = blockIdx.y * 128, n0 = blockIdx.x * 128;
    float acc[4][4][4] = {};
    proj_core(g_Ch + (size_t)m0 * EMB, g_Cl + (size_t)m0 * EMB,
              g_woh + (size_t)n0 * EMB, g_wol + (size_t)n0 * EMB, EMB, EMB, 32, sb, acc);
    const int lane = threadIdx.x & 31, wid = threadIdx.x >> 5;
    const int wm = wid >> 2, wn = wid & 3;
    #pragma unroll
    for (int mi = 0; mi < 4; ++mi) {
        #pragma unroll
        for (int ni = 0; ni < 4; ++ni) {
            int n = n0 + wn * 32 + ni * 8 + (lane & 3) * 2;
            float b0v = bias[n], b1v = bias[n + 1];
            #pragma unroll
            for (int half = 0; half < 2; ++half) {
                int m = m0 + wm * 64 + mi * 16 + (lane >> 2) + half * 8;
                float2 v = make_float2(acc[mi][ni][half*2] + b0v, acc[mi][ni][half*2+1] + b1v);
                *(float2*)(out + (size_t)m * EMB + n) = v;
            }
        }
    }
}

// V[bh][l][d] -> Vt[bh][d][l] (hi and lo)
__global__ void __launch_bounds__(256) transpose_v() {
    __shared__ bf16 t[64][66];
    const int bh = blockIdx.y, l0 = blockIdx.x * 64;
    #pragma unroll
    for (int a = 0; a < 2; ++a) {
        const bf16* src = (a ? g_Vl : g_Vh) + ((size_t)bh * LSEQ + l0) * HDIM;
        bf16* dst = (a ? g_Vtl : g_Vth) + (size_t)bh * HDIM * LSEQ;
        __syncthreads();
        for (int u = threadIdx.x; u < 64 * 32; u += 256) {
            int r = u >> 5, cu = u & 31;
            bf162 w = *(const bf162*)(src + (size_t)r * HDIM + cu * 2);
            t[r][cu * 2] = w.x; t[r][cu * 2 + 1] = w.y;
        }
        __syncthreads();
        for (int u = threadIdx.x; u < 64 * 32; u += 256) {
            int d = u >> 5, cl = u & 31;
            bf162 o;
            o.x = t[cl * 2][d]; o.y = t[cl * 2 + 1][d];
            *(bf162*)(dst + (size_t)d * LSEQ + l0 + cl * 2) = o;
        }
    }
}

// ---------------- fused flash attention ----------------
// smem: Qh@0 (16K), Ql@16K, stages@32K + st*32K {Kh,Kl,Vth,Vtl 8K each}, mask@96K (2x64 f32)
#define NT (LSEQ/64)
__device__ __forceinline__ void attn_prefetch(uint32_t sb, int t,
    const bf16* Kh, const bf16* Kl, const bf16* Vh, const bf16* Vl)
{
    const int tid = threadIdx.x;
    const int s0 = t * 64;
    const uint32_t b0 = sb + 32768u + (uint32_t)(t & 1) * 32768u;
    #pragma unroll
    for (int it = 0; it < 8; ++it) {
        int u = it * 256 + tid;
        int op = u >> 9, idx = u & 511;
        int row = idx >> 3, c = idx & 7;
        uint32_t off = (uint32_t)(row * 128 + c * 16);
        const void* s;
        if (op == 0)      s = Kh + (size_t)(s0 + row) * HDIM + c * 8;
        else if (op == 1) s = Kl + (size_t)(s0 + row) * HDIM + c * 8;
        else if (op == 2) s = Vh + (size_t)row * LSEQ + s0 + c * 8;
        else              s = Vl + (size_t)row * LSEQ + s0 + c * 8;
        CPA16(b0 + (uint32_t)op * 8192u + SW128(off), s);
    }
    CPCOMMIT();
}

__global__ void __launch_bounds__(256) attn_mma(const unsigned char* __restrict__ mask) {
    extern __shared__ char sm[];
    uint32_t sb = smem_u32(sm);
    float* smb = (float*)(sm + 98304);   // [2][64]
    const int tid = threadIdx.x, lane = tid & 31, wid = tid >> 5;
    const int q0 = blockIdx.x * 128, bh = blockIdx.y, b = bh >> 4, h = bh & 15;
    const bf16* Qhp = g_Qh + ((size_t)bh * LSEQ + q0) * HDIM;
    const bf16* Qlp = g_Ql + ((size_t)bh * LSEQ + q0) * HDIM;
    const bf16* Khp = g_Kh + (size_t)bh * LSEQ * HDIM;
    const bf16* Klp = g_Kl + (size_t)bh * LSEQ * HDIM;
    const bf16* Vhp = g_Vth + (size_t)bh * HDIM * LSEQ;
    const bf16* Vlp = g_Vtl + (size_t)bh * HDIM * LSEQ;

    // Q tiles + stage 0 (group 0)
    #pragma unroll
    for (int it = 0; it < 8; ++it) {
        int u = it * 256 + tid;
        const bf16* src = (u < 1024) ? Qhp : Qlp;
        int idx = u & 1023;
        int row = idx >> 3, c = idx & 7;
        uint32_t off = (uint32_t)(row * 128 + c * 16);
        CPA16(sb + (u < 1024 ? 0u : 16384u) + SW128(off), src + (size_t)row * HDIM + c * 8);
    }
    attn_prefetch(sb, 0, Khp, Klp, Vhp, Vlp);
    if (tid < 64) smb[tid] = mask[(size_t)tid * BATCH + b] ? -1e30f : 0.0f;

    float m0s = -1e30f, m1s = -1e30f, l0s = 0.f, l1s = 0.f;
    float o[8][4] = {};
    uint32_t qh[4][4], ql[4][4];

    const int arow = lane & 15;
    const uint32_t acolh = (uint32_t)((lane >> 4) * 16);
    const int brow = (lane & 7) + ((lane >> 4) << 3);
    const uint32_t bcolh = (uint32_t)(((lane >> 3) & 1) * 16);

    for (int t = 0; t < NT; ++t) {
        CPWAIT(0);
        __syncthreads();
        if (t + 1 < NT) {
            attn_prefetch(sb, t + 1, Khp, Klp, Vhp, Vlp);
            if (tid < 64)
                smb[((t + 1) & 1) * 64 + tid] =
                    mask[(size_t)((t + 1) * 64 + tid) * BATCH + b] ? -1e30f : 0.0f;
        }
        const float* smbt = smb + (t & 1) * 64;
        if (t == 0) {
            #pragma unroll
            for (int s = 0; s < 4; ++s) {
                uint32_t off = (uint32_t)((wid * 16 + arow) * 128 + s * 32) + acolh;
                uint32_t sw = SW128(off);
                LDSM4(qh[s][0], qh[s][1], qh[s][2], qh[s][3], sb + sw);
                LDSM4(ql[s][0], ql[s][1], ql[s][2], ql[s][3], sb + 16384u + sw);
            }
        }
        const uint32_t kb = sb + 32768u + (uint32_t)(t & 1) * 32768u;

        // S = Q K^T  (16 rows x 64 keys per warp)
        float sacc[8][4] = {};
        #pragma unroll
        for (int s = 0; s < 4; ++s) {
            uint32_t kh[8][2], kl[8][2];
            #pragma unroll
            for (int p = 0; p < 4; ++p) {
                uint32_t off = (uint32_t)((p * 16 + brow) * 128 + s * 32) + bcolh;
                uint32_t sw = SW128(off);
                LDSM4(kh[2*p][0], kh[2*p][1], kh[2*p+1][0], kh[2*p+1][1], kb + sw);
                LDSM4(kl[2*p][0], kl[2*p][1], kl[2*p+1][0], kl[2*p+1][1], kb + 8192u + sw);
            }
            #pragma unroll
            for (int ni = 0; ni < 8; ++ni) {
                MMA16(sacc[ni], qh[s], kh[ni]);
                MMA16(sacc[ni], qh[s], kl[ni]);
                MMA16(sacc[ni], ql[s], kh[ni]);
            }
        }

        // mask + online softmax (rows r0 = lane>>2, r0+8)
        float mx0 = -1e30f, mx1 = -1e30f;
        #pragma unroll
        for (int ni = 0; ni < 8; ++ni) {
            float mb0 = smbt[ni * 8 + (lane & 3) * 2];
            float mb1 = smbt[ni * 8 + (lane & 3) * 2 + 1];
            sacc[ni][0] += mb0; sacc[ni][1] += mb1;
            sacc[ni][2] += mb0; sacc[ni][3] += mb1;
            mx0 = fmaxf(mx0, fmaxf(sacc[ni][0], sacc[ni][1]));
            mx1 = fmaxf(mx1, fmaxf(sacc[ni][2], sacc[ni][3]));
        }
        mx0 = fmaxf(mx0, __shfl_xor_sync(0xffffffffu, mx0, 1));
        mx0 = fmaxf(mx0, __shfl_xor_sync(0xffffffffu, mx0, 2));
        mx1 = fmaxf(mx1, __shfl_xor_sync(0xffffffffu, mx1, 1));
        mx1 = fmaxf(mx1, __shfl_xor_sync(0xffffffffu, mx1, 2));
        float mn0 = fmaxf(m0s, mx0), mn1 = fmaxf(m1s, mx1);
        float al0 = __expf(m0s - mn0), al1 = __expf(m1s - mn1);
        float su0 = 0.f, su1 = 0.f;
        #pragma unroll
        for (int ni = 0; ni < 8; ++ni) {
            sacc[ni][0] = __expf(sacc[ni][0] - mn0);
            sacc[ni][1] = __expf(sacc[ni][1] - mn0);
            sacc[ni][2] = __expf(sacc[ni][2] - mn1);
            sacc[ni][3] = __expf(sacc[ni][3] - mn1);
            su0 += sacc[ni][0] + sacc[ni][1];
            su1 += sacc[ni][2] + sacc[ni][3];
        }
        su0 += __shfl_xor_sync(0xffffffffu, su0, 1);
        su0 += __shfl_xor_sync(0xffffffffu, su0, 2);
        su1 += __shfl_xor_sync(0xffffffffu, su1, 1);
        su1 += __shfl_xor_sync(0xffffffffu, su1, 2);
        m0s = mn0; m1s = mn1;
        l0s = l0s * al0 + su0; l1s = l1s * al1 + su1;
        #pragma unroll
        for (int di = 0; di < 8; ++di) {
            o[di][0] *= al0; o[di][1] *= al0;
            o[di][2] *= al1; o[di][3] *= al1;
        }

        // O += P V  (P from sacc via C->A frag identity, split hi/lo)
        #pragma unroll
        for (int s = 0; s < 4; ++s) {
            uint32_t ph[4], pl[4];
            packsplit(sacc[2*s][0],   sacc[2*s][1],   ph[0], pl[0]);
            packsplit(sacc[2*s][2],   sacc[2*s][3],   ph[1], pl[1]);
            packsplit(sacc[2*s+1][0], sacc[2*s+1][1], ph[2], pl[2]);
            packsplit(sacc[2*s+1][2], sacc[2*s+1][3], ph[3], pl[3]);
            uint32_t vh[8][2], vl[8][2];
            #pragma unroll
            for (int p = 0; p < 4; ++p) {
                uint32_t off = (uint32_t)((p * 16 + brow) * 128 + s * 32) + bcolh;
                uint32_t sw = SW128(off);
                LDSM4(vh[2*p][0], vh[2*p][1], vh[2*p+1][0], vh[2*p+1][1], kb + 16384u + sw);
                LDSM4(vl[2*p][0], vl[2*p][1], vl[2*p+1][0], vl[2*p+1][1], kb + 24576u + sw);
            }
            #pragma unroll
            for (int di = 0; di < 8; ++di) {
                MMA16(o[di], ph, vh[di]);
                MMA16(o[di], pl, vh[di]);
                MMA16(o[di], ph, vl[di]);
            }
        }
    }

    // normalize + write ctx (hi/lo split, token-major)
    float inv0 = 1.f / l0s, inv1 = 1.f / l1s;
    int r0 = q0 + wid * 16 + (lane >> 2);
    #pragma unroll
    for (int di = 0; di < 8; ++di) {
        int col = h * 64 + di * 8 + (lane & 3) * 2;
        bf162 hi, lo;
        split2(o[di][0] * inv0, o[di][1] * inv0, hi, lo);
        size_t off0 = (size_t)(r0 * BATCH + b) * EMB + col;
        *(bf162*)(g_Ch + off0) = hi; *(bf162*)(g_Cl + off0) = lo;
        split2(o[di][2] * inv1, o[di][3] * inv1, hi, lo);
        size_t off1 = (size_t)((r0 + 8) * BATCH + b) * EMB + col;
        *(bf162*)(g_Ch + off1) = hi; *(bf162*)(g_Cl + off1) = lo;
    }
}

// ---------------- launch ----------------
extern "C" void kernel_launch(void* const* d_in, const int* in_sizes, int n_in,
                              void* d_out, int out_size)
{
    const float* x     = (const float*)d_in[0];
    const float* w_in  = (const float*)d_in[1];
    const float* b_in  = (const float*)d_in[2];
    const float* w_out = (const float*)d_in[3];
    const float* b_out = (const float*)d_in[4];
    const unsigned char* mask = (const unsigned char*)d_in[5];
    float* out = (float*)d_out;

    constexpr int SMEM_PROJ = 98304;          // 3 stages x 32KB
    constexpr int SMEM_ATTN = 98304 + 512;    // Q 32K + 2 stages x 32K + mask 2x64 f32
    cudaFuncSetAttribute(qkv_mma,  cudaFuncAttributeMaxDynamicSharedMemorySize, SMEM_PROJ);
    cudaFuncSetAttribute(out_mma,  cudaFuncAttributeMaxDynamicSharedMemorySize, SMEM_PROJ);
    cudaFuncSetAttribute(attn_mma, cudaFuncAttributeMaxDynamicSharedMemorySize, SMEM_ATTN);

    bf16 *xh, *xl, *wih, *wil, *woh, *wol;
    cudaGetSymbolAddress((void**)&xh,  g_xh);  cudaGetSymbolAddress((void**)&xl,  g_xl);
    cudaGetSymbolAddress((void**)&wih, g_wih); cudaGetSymbolAddress((void**)&wil, g_wil);
    cudaGetSymbolAddress((void**)&woh, g_woh); cudaGetSymbolAddress((void**)&wol, g_wol);

    split_fp32<<<(MTOK*EMB/4 + 255)/256, 256>>>(x,     xh,  xl,  MTOK*EMB/4);
    split_fp32<<<(NQKV*EMB/4 + 255)/256, 256>>>(w_in,  wih, wil, NQKV*EMB/4);
    split_fp32<<<(EMB*EMB/4  + 255)/256, 256>>>(w_out, woh, wol, EMB*EMB/4);

    qkv_mma<<<dim3(NQKV/128, MTOK/128), 256, SMEM_PROJ>>>(b_in);
    transpose_v<<<dim3(LSEQ/64, BHN), 256>>>();
    attn_mma<<<dim3(LSEQ/128, BHN), 256, SMEM_ATTN>>>(mask);
    out_mma<<<dim3(EMB/128, MTOK/128), 256, SMEM_PROJ>>>(b_out, out);
}

// round 5
// speedup vs baseline: 3.3349x; 1.0083x over previous
#include <cuda_runtime.h>
#include <cuda_bf16.h>
#include <math.h>
#include <cstdint>

#define LSEQ 2048
#define BATCH 4
#define EMB 1024
#define HEADS 16
#define HDIM 64
#define MTOK 8192
#define NQKV 3072
#define BHN (BATCH*HEADS)

typedef __nv_bfloat16 bf16;
typedef __nv_bfloat162 bf162;

// ---------------- device scratch (allocation-free) ----------------
__device__ __align__(256) bf16 g_xh[(size_t)MTOK*EMB],  g_xl[(size_t)MTOK*EMB];
__device__ __align__(256) bf16 g_wih[(size_t)NQKV*EMB], g_wil[(size_t)NQKV*EMB];
__device__ __align__(256) bf16 g_woh[(size_t)EMB*EMB],  g_wol[(size_t)EMB*EMB];
__device__ __align__(256) bf16 g_Qh[(size_t)BHN*LSEQ*HDIM], g_Ql[(size_t)BHN*LSEQ*HDIM];
__device__ __align__(256) bf16 g_Kh[(size_t)BHN*LSEQ*HDIM], g_Kl[(size_t)BHN*LSEQ*HDIM];
__device__ __align__(256) bf16 g_Vh[(size_t)BHN*LSEQ*HDIM], g_Vl[(size_t)BHN*LSEQ*HDIM];
__device__ __align__(256) bf16 g_Vth[(size_t)BHN*HDIM*LSEQ], g_Vtl[(size_t)BHN*HDIM*LSEQ];
__device__ __align__(256) bf16 g_Ch[(size_t)MTOK*EMB], g_Cl[(size_t)MTOK*EMB];

// ---------------- helpers ----------------
__device__ __forceinline__ uint32_t smem_u32(const void* p) {
    uint32_t a;
    asm("{ .reg .u64 t; cvta.to.shared.u64 t, %1; cvt.u32.u64 %0, t; }" : "=r"(a) : "l"(p));
    return a;
}
#define CPA16(dst, src) asm volatile("cp.async.cg.shared.global [%0], [%1], 16;" :: "r"(dst), "l"(src))
#define CPCOMMIT()      asm volatile("cp.async.commit_group;")
#define CPWAIT(n)       asm volatile("cp.async.wait_group %0;" :: "n"(n))
#define LDSM4(r0,r1,r2,r3,a) \
    asm volatile("ldmatrix.sync.aligned.m8n8.x4.shared.b16 {%0,%1,%2,%3}, [%4];" \
        : "=r"(r0),"=r"(r1),"=r"(r2),"=r"(r3) : "r"(a))
#define MMA16(d,a,b) \
    asm volatile("mma.sync.aligned.m16n8k16.row.col.f32.bf16.bf16.f32 " \
        "{%0,%1,%2,%3},{%4,%5,%6,%7},{%8,%9},{%0,%1,%2,%3};" \
        : "+f"((d)[0]),"+f"((d)[1]),"+f"((d)[2]),"+f"((d)[3]) \
        : "r"((a)[0]),"r"((a)[1]),"r"((a)[2]),"r"((a)[3]),"r"((b)[0]),"r"((b)[1]))
#define SW64(o)  ((o) ^ (((o)>>3)&0x30))
#define SW128(o) ((o) ^ (((o)>>3)&0x70))

__device__ __forceinline__ void split2(float x, float y, bf162& hi, bf162& lo) {
    hi.x = __float2bfloat16_rn(x); hi.y = __float2bfloat16_rn(y);
    lo.x = __float2bfloat16_rn(x - __bfloat162float(hi.x));
    lo.y = __float2bfloat16_rn(y - __bfloat162float(hi.y));
}
__device__ __forceinline__ void packsplit(float x, float y, uint32_t& hi, uint32_t& lo) {
    bf162 h, l; split2(x, y, h, l);
    hi = *(uint32_t*)&h; lo = *(uint32_t*)&l;
}

// ---------------- projection GEMM core (C = A·B^T, 3-term bf16 split) ----------
// block 128x128, 512 thr (16 warps 4x4, warp tile 32x32), K-chunks of 32,
// 3-stage cp.async ring. stage (32KB): Ah@0, Al@8K, Bh@16K, Bl@24K; SW64.
__device__ __forceinline__ void proj_prefetch(uint32_t sbase, int ch,
    const bf16* Ah, const bf16* Al, const bf16* Bh, const bf16* Bl, int lda, int ldb)
{
    const int tid = threadIdx.x;
    const uint32_t b0 = sbase + (uint32_t)(ch % 3) * 32768u;
    #pragma unroll
    for (int it = 0; it < 4; ++it) {
        int u = it * 512 + tid;
        int op = u >> 9;
        int row = (u >> 2) & 127;
        int c = u & 3;
        const bf16* src = (op == 0) ? Ah : (op == 1) ? Al : (op == 2) ? Bh : Bl;
        int ld = (op < 2) ? lda : ldb;
        const void* s = src + (size_t)row * ld + ch * 32 + c * 8;
        uint32_t off = (uint32_t)(row * 64 + c * 16);
        CPA16(b0 + (uint32_t)op * 8192u + SW64(off), s);
    }
    CPCOMMIT();
}

__device__ __forceinline__ void proj_core(const bf16* Ah, const bf16* Al,
    const bf16* Bh, const bf16* Bl, int lda, int ldb, int nch,
    uint32_t sbase, float acc[2][4][4])
{
    const int tid = threadIdx.x, lane = tid & 31, wid = tid >> 5;
    const int wm = wid >> 2, wn = wid & 3;
    const int arow = lane & 15;
    const uint32_t acolh = (uint32_t)((lane >> 4) * 16);
    const int brow = (lane & 7) + ((lane >> 4) << 3);
    const uint32_t bcolh = (uint32_t)(((lane >> 3) & 1) * 16);

    proj_prefetch(sbase, 0, Ah, Al, Bh, Bl, lda, ldb);
    proj_prefetch(sbase, 1, Ah, Al, Bh, Bl, lda, ldb);
    for (int ch = 0; ch < nch; ++ch) {
        if (ch + 1 < nch) CPWAIT(1); else CPWAIT(0);
        __syncthreads();
        if (ch + 2 < nch) proj_prefetch(sbase, ch + 2, Ah, Al, Bh, Bl, lda, ldb);
        const uint32_t b0 = sbase + (uint32_t)(ch % 3) * 32768u;
        #pragma unroll
        for (int s = 0; s < 2; ++s) {
            uint32_t ah[2][4], al[2][4], bh[4][2], bl[4][2];
            #pragma unroll
            for (int mi = 0; mi < 2; ++mi) {
                uint32_t off = (uint32_t)((wm * 32 + mi * 16 + arow) * 64 + s * 32) + acolh;
                uint32_t sw = SW64(off);
                LDSM4(ah[mi][0], ah[mi][1], ah[mi][2], ah[mi][3], b0 + sw);
                LDSM4(al[mi][0], al[mi][1], al[mi][2], al[mi][3], b0 + 8192u + sw);
            }
            #pragma unroll
            for (int p = 0; p < 2; ++p) {
                uint32_t off = (uint32_t)((wn * 32 + p * 16 + brow) * 64 + s * 32) + bcolh;
                uint32_t sw = SW64(off);
                LDSM4(bh[2*p][0], bh[2*p][1], bh[2*p+1][0], bh[2*p+1][1], b0 + 16384u + sw);
                LDSM4(bl[2*p][0], bl[2*p][1], bl[2*p+1][0], bl[2*p+1][1], b0 + 24576u + sw);
            }
            #pragma unroll
            for (int mi = 0; mi < 2; ++mi)
                #pragma unroll
                for (int ni = 0; ni < 4; ++ni) {
                    MMA16(acc[mi][ni], ah[mi], bh[ni]);
                    MMA16(acc[mi][ni], ah[mi], bl[ni]);
                    MMA16(acc[mi][ni], al[mi], bh[ni]);
                }
        }
    }
}

// ---------------- kernels ----------------
__global__ void __launch_bounds__(256) split_fp32(const float* __restrict__ src,
                                                  bf16* __restrict__ hi,
                                                  bf16* __restrict__ lo, int n4) {
    int i = blockIdx.x * 256 + threadIdx.x;
    if (i >= n4) return;
    float4 v = ((const float4*)src)[i];
    bf162 h0, l0, h1, l1;
    split2(v.x, v.y, h0, l0);
    split2(v.z, v.w, h1, l1);
    ((bf162*)hi)[2*i] = h0; ((bf162*)hi)[2*i+1] = h1;
    ((bf162*)lo)[2*i] = l0; ((bf162*)lo)[2*i+1] = l1;
}

__global__ void __launch_bounds__(512) qkv_mma(const float* __restrict__ bias) {
    extern __shared__ char sm[];
    uint32_t sb = smem_u32(sm);
    const int m0 = blockIdx.y * 128, n0 = blockIdx.x * 128;
    float acc[2][4][4] = {};
    proj_core(g_xh + (size_t)m0 * EMB, g_xl + (size_t)m0 * EMB,
              g_wih + (size_t)n0 * EMB, g_wil + (size_t)n0 * EMB, EMB, EMB, 32, sb, acc);
    const int lane = threadIdx.x & 31, wid = threadIdx.x >> 5;
    const int wm = wid >> 2, wn = wid & 3;
    const int sec = n0 >> 10;
    bf16* dh = sec == 0 ? g_Qh : sec == 1 ? g_Kh : g_Vh;
    bf16* dl = sec == 0 ? g_Ql : sec == 1 ? g_Kl : g_Vl;
    const float scale = sec == 0 ? 0.125f : 1.0f;
    #pragma unroll
    for (int mi = 0; mi < 2; ++mi) {
        #pragma unroll
        for (int ni = 0; ni < 4; ++ni) {
            int n = n0 + wn * 32 + ni * 8 + (lane & 3) * 2;
            int h = (n & 1023) >> 6, dd = n & 63;
            float b0v = bias[n], b1v = bias[n + 1];
            #pragma unroll
            for (int half = 0; half < 2; ++half) {
                int m = m0 + wm * 32 + mi * 16 + (lane >> 2) + half * 8;
                int l = m >> 2, bb = m & 3;
                float v0 = (acc[mi][ni][half*2]     + b0v) * scale;
                float v1 = (acc[mi][ni][half*2 + 1] + b1v) * scale;
                bf162 hi, lo; split2(v0, v1, hi, lo);
                size_t off = (((size_t)(bb * HEADS + h)) * LSEQ + l) * HDIM + dd;
                *(bf162*)(dh + off) = hi; *(bf162*)(dl + off) = lo;
            }
        }
    }
}

__global__ void __launch_bounds__(512) out_mma(const float* __restrict__ bias,
                                               float* __restrict__ out) {
    extern __shared__ char sm[];
    uint32_t sb = smem_u32(sm);
    const int m0 = blockIdx.y * 128, n0 = blockIdx.x * 128;
    float acc[2][4][4] = {};
    proj_core(g_Ch + (size_t)m0 * EMB, g_Cl + (size_t)m0 * EMB,
              g_woh + (size_t)n0 * EMB, g_wol + (size_t)n0 * EMB, EMB, EMB, 32, sb, acc);
    const int lane = threadIdx.x & 31, wid = threadIdx.x >> 5;
    const int wm = wid >> 2, wn = wid & 3;
    #pragma unroll
    for (int mi = 0; mi < 2; ++mi) {
        #pragma unroll
        for (int ni = 0; ni < 4; ++ni) {
            int n = n0 + wn * 32 + ni * 8 + (lane & 3) * 2;
            float b0v = bias[n], b1v = bias[n + 1];
            #pragma unroll
            for (int half = 0; half < 2; ++half) {
                int m = m0 + wm * 32 + mi * 16 + (lane >> 2) + half * 8;
                float2 v = make_float2(acc[mi][ni][half*2] + b0v, acc[mi][ni][half*2+1] + b1v);
                *(float2*)(out + (size_t)m * EMB + n) = v;
            }
        }
    }
}

// V[bh][l][d] -> Vt[bh][d][l] (hi and lo)
__global__ void __launch_bounds__(256) transpose_v() {
    __shared__ bf16 t[64][66];
    const int bh = blockIdx.y, l0 = blockIdx.x * 64;
    #pragma unroll
    for (int a = 0; a < 2; ++a) {
        const bf16* src = (a ? g_Vl : g_Vh) + ((size_t)bh * LSEQ + l0) * HDIM;
        bf16* dst = (a ? g_Vtl : g_Vth) + (size_t)bh * HDIM * LSEQ;
        __syncthreads();
        for (int u = threadIdx.x; u < 64 * 32; u += 256) {
            int r = u >> 5, cu = u & 31;
            bf162 w = *(const bf162*)(src + (size_t)r * HDIM + cu * 2);
            t[r][cu * 2] = w.x; t[r][cu * 2 + 1] = w.y;
        }
        __syncthreads();
        for (int u = threadIdx.x; u < 64 * 32; u += 256) {
            int d = u >> 5, cl = u & 31;
            bf162 o;
            o.x = t[cl * 2][d]; o.y = t[cl * 2 + 1][d];
            *(bf162*)(dst + (size_t)d * LSEQ + l0 + cl * 2) = o;
        }
    }
}

// ---------------- fused flash attention ----------------
// 512 thr, 16 warps x 16 q-rows = 256 q-rows per CTA.
// smem: Qh@0 (32K), Ql@32K, stages@64K + (t&1)*32K {Kh,Kl,Vth,Vtl 8K each}, mask@128K (2x64 f32)
#define NT (LSEQ/64)
__device__ __forceinline__ void attn_prefetch(uint32_t sb, int t,
    const bf16* Kh, const bf16* Kl, const bf16* Vh, const bf16* Vl)
{
    const int tid = threadIdx.x;
    const int s0 = t * 64;
    const uint32_t b0 = sb + 65536u + (uint32_t)(t & 1) * 32768u;
    #pragma unroll
    for (int it = 0; it < 4; ++it) {
        int u = it * 512 + tid;
        int op = u >> 9, idx = u & 511;
        int row = idx >> 3, c = idx & 7;
        uint32_t off = (uint32_t)(row * 128 + c * 16);
        const void* s;
        if (op == 0)      s = Kh + (size_t)(s0 + row) * HDIM + c * 8;
        else if (op == 1) s = Kl + (size_t)(s0 + row) * HDIM + c * 8;
        else if (op == 2) s = Vh + (size_t)row * LSEQ + s0 + c * 8;
        else              s = Vl + (size_t)row * LSEQ + s0 + c * 8;
        CPA16(b0 + (uint32_t)op * 8192u + SW128(off), s);
    }
    CPCOMMIT();
}

__global__ void __launch_bounds__(512) attn_mma(const unsigned char* __restrict__ mask) {
    extern __shared__ char sm[];
    uint32_t sb = smem_u32(sm);
    float* smb = (float*)(sm + 131072);   // [2][64]
    const int tid = threadIdx.x, lane = tid & 31, wid = tid >> 5;
    const int q0 = blockIdx.x * 256, bh = blockIdx.y, b = bh >> 4, h = bh & 15;
    const bf16* Qhp = g_Qh + ((size_t)bh * LSEQ + q0) * HDIM;
    const bf16* Qlp = g_Ql + ((size_t)bh * LSEQ + q0) * HDIM;
    const bf16* Khp = g_Kh + (size_t)bh * LSEQ * HDIM;
    const bf16* Klp = g_Kl + (size_t)bh * LSEQ * HDIM;
    const bf16* Vhp = g_Vth + (size_t)bh * HDIM * LSEQ;
    const bf16* Vlp = g_Vtl + (size_t)bh * HDIM * LSEQ;

    // Q tiles (256 rows x 64, hi/lo) + stage 0
    #pragma unroll
    for (int it = 0; it < 8; ++it) {
        int u = it * 512 + tid;
        const bf16* src = (u < 2048) ? Qhp : Qlp;
        int idx = u & 2047;
        int row = idx >> 3, c = idx & 7;
        uint32_t off = (uint32_t)(row * 128 + c * 16);
        CPA16(sb + (u < 2048 ? 0u : 32768u) + SW128(off), src + (size_t)row * HDIM + c * 8);
    }
    CPCOMMIT();
    attn_prefetch(sb, 0, Khp, Klp, Vhp, Vlp);
    if (tid < 64) smb[tid] = mask[(size_t)tid * BATCH + b] ? -1e30f : 0.0f;

    float m0s = -1e30f, m1s = -1e30f, l0s = 0.f, l1s = 0.f;
    float o[8][4] = {};

    const int arow = lane & 15;
    const uint32_t acolh = (uint32_t)((lane >> 4) * 16);
    const int brow = (lane & 7) + ((lane >> 4) << 3);
    const uint32_t bcolh = (uint32_t)(((lane >> 3) & 1) * 16);

    for (int t = 0; t < NT; ++t) {
        CPWAIT(0);
        __syncthreads();
        if (t + 1 < NT) {
            attn_prefetch(sb, t + 1, Khp, Klp, Vhp, Vlp);
            if (tid < 64)
                smb[((t + 1) & 1) * 64 + tid] =
                    mask[(size_t)((t + 1) * 64 + tid) * BATCH + b] ? -1e30f : 0.0f;
        }
        const float* smbt = smb + (t & 1) * 64;
        const uint32_t kb = sb + 65536u + (uint32_t)(t & 1) * 32768u;

        // S = Q K^T  (16 rows x 64 keys per warp); Q frags reloaded per s-iter
        float sacc[8][4] = {};
        #pragma unroll
        for (int s = 0; s < 4; ++s) {
            uint32_t qhs[4], qls[4];
            {
                uint32_t off = (uint32_t)((wid * 16 + arow) * 128 + s * 32) + acolh;
                uint32_t sw = SW128(off);
                LDSM4(qhs[0], qhs[1], qhs[2], qhs[3], sb + sw);
                LDSM4(qls[0], qls[1], qls[2], qls[3], sb + 32768u + sw);
            }
            uint32_t kh[8][2], kl[8][2];
            #pragma unroll
            for (int p = 0; p < 4; ++p) {
                uint32_t off = (uint32_t)((p * 16 + brow) * 128 + s * 32) + bcolh;
                uint32_t sw = SW128(off);
                LDSM4(kh[2*p][0], kh[2*p][1], kh[2*p+1][0], kh[2*p+1][1], kb + sw);
                LDSM4(kl[2*p][0], kl[2*p][1], kl[2*p+1][0], kl[2*p+1][1], kb + 8192u + sw);
            }
            #pragma unroll
            for (int ni = 0; ni < 8; ++ni) {
                MMA16(sacc[ni], qhs, kh[ni]);
                MMA16(sacc[ni], qhs, kl[ni]);
                MMA16(sacc[ni], qls, kh[ni]);
            }
        }

        // mask + online softmax (rows r0 = lane>>2, r0+8)
        float mx0 = -1e30f, mx1 = -1e30f;
        #pragma unroll
        for (int ni = 0; ni < 8; ++ni) {
            float mb0 = smbt[ni * 8 + (lane & 3) * 2];
            float mb1 = smbt[ni * 8 + (lane & 3) * 2 + 1];
            sacc[ni][0] += mb0; sacc[ni][1] += mb1;
            sacc[ni][2] += mb0; sacc[ni][3] += mb1;
            mx0 = fmaxf(mx0, fmaxf(sacc[ni][0], sacc[ni][1]));
            mx1 = fmaxf(mx1, fmaxf(sacc[ni][2], sacc[ni][3]));
        }
        mx0 = fmaxf(mx0, __shfl_xor_sync(0xffffffffu, mx0, 1));
        mx0 = fmaxf(mx0, __shfl_xor_sync(0xffffffffu, mx0, 2));
        mx1 = fmaxf(mx1, __shfl_xor_sync(0xffffffffu, mx1, 1));
        mx1 = fmaxf(mx1, __shfl_xor_sync(0xffffffffu, mx1, 2));
        float mn0 = fmaxf(m0s, mx0), mn1 = fmaxf(m1s, mx1);
        float al0 = __expf(m0s - mn0), al1 = __expf(m1s - mn1);
        float su0 = 0.f, su1 = 0.f;
        #pragma unroll
        for (int ni = 0; ni < 8; ++ni) {
            sacc[ni][0] = __expf(sacc[ni][0] - mn0);
            sacc[ni][1] = __expf(sacc[ni][1] - mn0);
            sacc[ni][2] = __expf(sacc[ni][2] - mn1);
            sacc[ni][3] = __expf(sacc[ni][3] - mn1);
            su0 += sacc[ni][0] + sacc[ni][1];
            su1 += sacc[ni][2] + sacc[ni][3];
        }
        su0 += __shfl_xor_sync(0xffffffffu, su0, 1);
        su0 += __shfl_xor_sync(0xffffffffu, su0, 2);
        su1 += __shfl_xor_sync(0xffffffffu, su1, 1);
        su1 += __shfl_xor_sync(0xffffffffu, su1, 2);
        m0s = mn0; m1s = mn1;
        l0s = l0s * al0 + su0; l1s = l1s * al1 + su1;
        #pragma unroll
        for (int di = 0; di < 8; ++di) {
            o[di][0] *= al0; o[di][1] *= al0;
            o[di][2] *= al1; o[di][3] *= al1;
        }

        // O += P V  (P from sacc via C->A frag identity, split hi/lo)
        #pragma unroll
        for (int s = 0; s < 4; ++s) {
            uint32_t ph[4], pl[4];
            packsplit(sacc[2*s][0],   sacc[2*s][1],   ph[0], pl[0]);
            packsplit(sacc[2*s][2],   sacc[2*s][3],   ph[1], pl[1]);
            packsplit(sacc[2*s+1][0], sacc[2*s+1][1], ph[2], pl[2]);
            packsplit(sacc[2*s+1][2], sacc[2*s+1][3], ph[3], pl[3]);
            uint32_t vh[8][2], vl[8][2];
            #pragma unroll
            for (int p = 0; p < 4; ++p) {
                uint32_t off = (uint32_t)((p * 16 + brow) * 128 + s * 32) + bcolh;
                uint32_t sw = SW128(off);
                LDSM4(vh[2*p][0], vh[2*p][1], vh[2*p+1][0], vh[2*p+1][1], kb + 16384u + sw);
                LDSM4(vl[2*p][0], vl[2*p][1], vl[2*p+1][0], vl[2*p+1][1], kb + 24576u + sw);
            }
            #pragma unroll
            for (int di = 0; di < 8; ++di) {
                MMA16(o[di], ph, vh[di]);
                MMA16(o[di], pl, vh[di]);
                MMA16(o[di], ph, vl[di]);
            }
        }
    }

    // normalize + write ctx (hi/lo split, token-major)
    float inv0 = 1.f / l0s, inv1 = 1.f / l1s;
    int r0 = q0 + wid * 16 + (lane >> 2);
    #pragma unroll
    for (int di = 0; di < 8; ++di) {
        int col = h * 64 + di * 8 + (lane & 3) * 2;
        bf162 hi, lo;
        split2(o[di][0] * inv0, o[di][1] * inv0, hi, lo);
        size_t off0 = (size_t)(r0 * BATCH + b) * EMB + col;
        *(bf162*)(g_Ch + off0) = hi; *(bf162*)(g_Cl + off0) = lo;
        split2(o[di][2] * inv1, o[di][3] * inv1, hi, lo);
        size_t off1 = (size_t)((r0 + 8) * BATCH + b) * EMB + col;
        *(bf162*)(g_Ch + off1) = hi; *(bf162*)(g_Cl + off1) = lo;
    }
}

// ---------------- launch ----------------
extern "C" void kernel_launch(void* const* d_in, const int* in_sizes, int n_in,
                              void* d_out, int out_size)
{
    const float* x     = (const float*)d_in[0];
    const float* w_in  = (const float*)d_in[1];
    const float* b_in  = (const float*)d_in[2];
    const float* w_out = (const float*)d_in[3];
    const float* b_out = (const float*)d_in[4];
    const unsigned char* mask = (const unsigned char*)d_in[5];
    float* out = (float*)d_out;

    constexpr int SMEM_PROJ = 98304;           // 3 stages x 32KB
    constexpr int SMEM_ATTN = 131072 + 512;    // Q 64K + 2 stages x 32K + mask
    cudaFuncSetAttribute(qkv_mma,  cudaFuncAttributeMaxDynamicSharedMemorySize, SMEM_PROJ);
    cudaFuncSetAttribute(out_mma,  cudaFuncAttributeMaxDynamicSharedMemorySize, SMEM_PROJ);
    cudaFuncSetAttribute(attn_mma, cudaFuncAttributeMaxDynamicSharedMemorySize, SMEM_ATTN);

    bf16 *xh, *xl, *wih, *wil, *woh, *wol;
    cudaGetSymbolAddress((void**)&xh,  g_xh);  cudaGetSymbolAddress((void**)&xl,  g_xl);
    cudaGetSymbolAddress((void**)&wih, g_wih); cudaGetSymbolAddress((void**)&wil, g_wil);
    cudaGetSymbolAddress((void**)&woh, g_woh); cudaGetSymbolAddress((void**)&wol, g_wol);

    split_fp32<<<(MTOK*EMB/4 + 255)/256, 256>>>(x,     xh,  xl,  MTOK*EMB/4);
    split_fp32<<<(NQKV*EMB/4 + 255)/256, 256>>>(w_in,  wih, wil, NQKV*EMB/4);
    split_fp32<<<(EMB*EMB/4  + 255)/256, 256>>>(w_out, woh, wol, EMB*EMB/4);

    qkv_mma<<<dim3(NQKV/128, MTOK/128), 512, SMEM_PROJ>>>(b_in);
    transpose_v<<<dim3(LSEQ/64, BHN), 256>>>();
    attn_mma<<<dim3(LSEQ/256, BHN), 512, SMEM_ATTN>>>(mask);
    out_mma<<<dim3(EMB/128, MTOK/128), 512, SMEM_PROJ>>>(b_out, out);
}

// round 7
// speedup vs baseline: 3.3750x; 1.0120x over previous
#include <cuda_runtime.h>
#include <cuda_bf16.h>
#include <math.h>
#include <cstdint>

#define LSEQ 2048
#define BATCH 4
#define EMB 1024
#define HEADS 16
#define HDIM 64
#define MTOK 8192
#define NQKV 3072
#define BHN (BATCH*HEADS)

typedef __nv_bfloat16 bf16;
typedef __nv_bfloat162 bf162;

// ---------------- device scratch (allocation-free) ----------------
__device__ __align__(256) bf16 g_xh[(size_t)MTOK*EMB],  g_xl[(size_t)MTOK*EMB];
__device__ __align__(256) bf16 g_wih[(size_t)NQKV*EMB], g_wil[(size_t)NQKV*EMB];
__device__ __align__(256) bf16 g_woh[(size_t)EMB*EMB],  g_wol[(size_t)EMB*EMB];
__device__ __align__(256) bf16 g_Qh[(size_t)BHN*LSEQ*HDIM], g_Ql[(size_t)BHN*LSEQ*HDIM];
__device__ __align__(256) bf16 g_Kh[(size_t)BHN*LSEQ*HDIM], g_Kl[(size_t)BHN*LSEQ*HDIM];
__device__ __align__(256) bf16 g_Vh[(size_t)BHN*LSEQ*HDIM], g_Vl[(size_t)BHN*LSEQ*HDIM];
__device__ __align__(256) bf16 g_Vth[(size_t)BHN*HDIM*LSEQ], g_Vtl[(size_t)BHN*HDIM*LSEQ];
__device__ __align__(256) bf16 g_Ch[(size_t)MTOK*EMB], g_Cl[(size_t)MTOK*EMB];

// ---------------- helpers ----------------
__device__ __forceinline__ uint32_t smem_u32(const void* p) {
    uint32_t a;
    asm("{ .reg .u64 t; cvta.to.shared.u64 t, %1; cvt.u32.u64 %0, t; }" : "=r"(a) : "l"(p));
    return a;
}
#define CPA16(dst, src) asm volatile("cp.async.cg.shared.global [%0], [%1], 16;" :: "r"(dst), "l"(src))
#define CPCOMMIT()      asm volatile("cp.async.commit_group;")
#define CPWAIT(n)       asm volatile("cp.async.wait_group %0;" :: "n"(n))
#define LDSM4(r0,r1,r2,r3,a) \
    asm volatile("ldmatrix.sync.aligned.m8n8.x4.shared.b16 {%0,%1,%2,%3}, [%4];" \
        : "=r"(r0),"=r"(r1),"=r"(r2),"=r"(r3) : "r"(a))
#define MMA16(d,a,b) \
    asm volatile("mma.sync.aligned.m16n8k16.row.col.f32.bf16.bf16.f32 " \
        "{%0,%1,%2,%3},{%4,%5,%6,%7},{%8,%9},{%0,%1,%2,%3};" \
        : "+f"((d)[0]),"+f"((d)[1]),"+f"((d)[2]),"+f"((d)[3]) \
        : "r"((a)[0]),"r"((a)[1]),"r"((a)[2]),"r"((a)[3]),"r"((b)[0]),"r"((b)[1]))
#define SW64(o)  ((o) ^ (((o)>>3)&0x30))
#define SW128(o) ((o) ^ (((o)>>3)&0x70))

__device__ __forceinline__ void split2(float x, float y, bf162& hi, bf162& lo) {
    hi.x = __float2bfloat16_rn(x); hi.y = __float2bfloat16_rn(y);
    lo.x = __float2bfloat16_rn(x - __bfloat162float(hi.x));
    lo.y = __float2bfloat16_rn(y - __bfloat162float(hi.y));
}
__device__ __forceinline__ void packsplit(float x, float y, uint32_t& hi, uint32_t& lo) {
    bf162 h, l; split2(x, y, h, l);
    hi = *(uint32_t*)&h; lo = *(uint32_t*)&l;
}

// ---------------- projection GEMM core (C = A·B^T, 3-term bf16 split) ----------
// block 128x256, 512 thr (16 warps 2x8, warp tile 64x32), K-chunks of 32,
// 3-stage cp.async ring. stage (48KB): Ah@0 (8K), Al@8K, Bh@16K (16K), Bl@32K; SW64.
#define PSTAGE 49152u
__device__ __forceinline__ void proj_prefetch(uint32_t sbase, int ch,
    const bf16* Ah, const bf16* Al, const bf16* Bh, const bf16* Bl, int lda, int ldb)
{
    const int tid = threadIdx.x;
    const uint32_t b0 = sbase + (uint32_t)(ch % 3) * PSTAGE;
    #pragma unroll
    for (int it = 0; it < 6; ++it) {
        int u = it * 512 + tid;
        const bf16* src; uint32_t roff; int a, ld;
        if (u < 1024) {
            src = (u < 512) ? Ah : Al; roff = (u < 512) ? 0u : 8192u;
            a = u & 511; ld = lda;
        } else {
            a = u - 1024;
            src = (a < 1024) ? Bh : Bl; roff = (a < 1024) ? 16384u : 32768u;
            a &= 1023; ld = ldb;
        }
        int row = a >> 2, c = u & 3;
        const void* s = src + (size_t)row * ld + ch * 32 + c * 8;
        uint32_t off = (uint32_t)(row * 64 + c * 16);
        CPA16(b0 + roff + SW64(off), s);
    }
    CPCOMMIT();
}

__device__ __forceinline__ void proj_core(const bf16* Ah, const bf16* Al,
    const bf16* Bh, const bf16* Bl, int lda, int ldb, int nch,
    uint32_t sbase, float acc[4][4][4])
{
    const int tid = threadIdx.x, lane = tid & 31, wid = tid >> 5;
    const int wm = wid >> 3, wn = wid & 7;
    const int arow = lane & 15;
    const uint32_t acolh = (uint32_t)((lane >> 4) * 16);
    const int brow = (lane & 7) + ((lane >> 4) << 3);
    const uint32_t bcolh = (uint32_t)(((lane >> 3) & 1) * 16);

    proj_prefetch(sbase, 0, Ah, Al, Bh, Bl, lda, ldb);
    proj_prefetch(sbase, 1, Ah, Al, Bh, Bl, lda, ldb);
    for (int ch = 0; ch < nch; ++ch) {
        if (ch + 1 < nch) CPWAIT(1); else CPWAIT(0);
        __syncthreads();
        if (ch + 2 < nch) proj_prefetch(sbase, ch + 2, Ah, Al, Bh, Bl, lda, ldb);
        const uint32_t b0 = sbase + (uint32_t)(ch % 3) * PSTAGE;
        #pragma unroll
        for (int s = 0; s < 2; ++s) {
            uint32_t ah[4][4], al[4][4], bh[4][2], bl[4][2];
            #pragma unroll
            for (int mi = 0; mi < 4; ++mi) {
                uint32_t off = (uint32_t)((wm * 64 + mi * 16 + arow) * 64 + s * 32) + acolh;
                uint32_t sw = SW64(off);
                LDSM4(ah[mi][0], ah[mi][1], ah[mi][2], ah[mi][3], b0 + sw);
                LDSM4(al[mi][0], al[mi][1], al[mi][2], al[mi][3], b0 + 8192u + sw);
            }
            #pragma unroll
            for (int p = 0; p < 2; ++p) {
                uint32_t off = (uint32_t)((wn * 32 + p * 16 + brow) * 64 + s * 32) + bcolh;
                uint32_t sw = SW64(off);
                LDSM4(bh[2*p][0], bh[2*p][1], bh[2*p+1][0], bh[2*p+1][1], b0 + 16384u + sw);
                LDSM4(bl[2*p][0], bl[2*p][1], bl[2*p+1][0], bl[2*p+1][1], b0 + 32768u + sw);
            }
            #pragma unroll
            for (int mi = 0; mi < 4; ++mi)
                #pragma unroll
                for (int ni = 0; ni < 4; ++ni) {
                    MMA16(acc[mi][ni], ah[mi], bh[ni]);
                    MMA16(acc[mi][ni], ah[mi], bl[ni]);
                    MMA16(acc[mi][ni], al[mi], bh[ni]);
                }
        }
    }
}

// ---------------- kernels ----------------
__global__ void __launch_bounds__(256) split_fp32(const float* __restrict__ src,
                                                  bf16* __restrict__ hi,
                                                  bf16* __restrict__ lo, int n4) {
    int i = blockIdx.x * 256 + threadIdx.x;
    if (i >= n4) return;
    float4 v = ((const float4*)src)[i];
    bf162 h0, l0, h1, l1;
    split2(v.x, v.y, h0, l0);
    split2(v.z, v.w, h1, l1);
    ((bf162*)hi)[2*i] = h0; ((bf162*)hi)[2*i+1] = h1;
    ((bf162*)lo)[2*i] = l0; ((bf162*)lo)[2*i+1] = l1;
}

__global__ void __launch_bounds__(512) qkv_mma(const float* __restrict__ bias) {
    extern __shared__ char sm[];
    uint32_t sb = smem_u32(sm);
    const int m0 = blockIdx.y * 128, n0 = blockIdx.x * 256;
    float acc[4][4][4] = {};
    proj_core(g_xh + (size_t)m0 * EMB, g_xl + (size_t)m0 * EMB,
              g_wih + (size_t)n0 * EMB, g_wil + (size_t)n0 * EMB, EMB, EMB, 32, sb, acc);
    const int lane = threadIdx.x & 31, wid = threadIdx.x >> 5;
    const int wm = wid >> 3, wn = wid & 7;
    #pragma unroll
    for (int mi = 0; mi < 4; ++mi) {
        #pragma unroll
        for (int ni = 0; ni < 4; ++ni) {
            int n = n0 + wn * 32 + ni * 8 + (lane & 3) * 2;
            const int sec = n >> 10;
            bf16* dh = sec == 0 ? g_Qh : sec == 1 ? g_Kh : g_Vh;
            bf16* dl = sec == 0 ? g_Ql : sec == 1 ? g_Kl : g_Vl;
            const float scale = sec == 0 ? 0.125f : 1.0f;
            int h = (n & 1023) >> 6, dd = n & 63;
            float b0v = bias[n], b1v = bias[n + 1];
            #pragma unroll
            for (int half = 0; half < 2; ++half) {
                int m = m0 + wm * 64 + mi * 16 + (lane >> 2) + half * 8;
                int l = m >> 2, bb = m & 3;
                float v0 = (acc[mi][ni][half*2]     + b0v) * scale;
                float v1 = (acc[mi][ni][half*2 + 1] + b1v) * scale;
                bf162 hi, lo; split2(v0, v1, hi, lo);
                size_t off = (((size_t)(bb * HEADS + h)) * LSEQ + l) * HDIM + dd;
                *(bf162*)(dh + off) = hi; *(bf162*)(dl + off) = lo;
            }
        }
    }
}

__global__ void __launch_bounds__(512) out_mma(const float* __restrict__ bias,
                                               float* __restrict__ out) {
    extern __shared__ char sm[];
    uint32_t sb = smem_u32(sm);
    const int m0 = blockIdx.y * 128, n0 = blockIdx.x * 256;
    float acc[4][4][4] = {};
    proj_core(g_Ch + (size_t)m0 * EMB, g_Cl + (size_t)m0 * EMB,
              g_woh + (size_t)n0 * EMB, g_wol + (size_t)n0 * EMB, EMB, EMB, 32, sb, acc);
    const int lane = threadIdx.x & 31, wid = threadIdx.x >> 5;
    const int wm = wid >> 3, wn = wid & 7;
    #pragma unroll
    for (int mi = 0; mi < 4; ++mi) {
        #pragma unroll
        for (int ni = 0; ni < 4; ++ni) {
            int n = n0 + wn * 32 + ni * 8 + (lane & 3) * 2;
            float b0v = bias[n], b1v = bias[n + 1];
            #pragma unroll
            for (int half = 0; half < 2; ++half) {
                int m = m0 + wm * 64 + mi * 16 + (lane >> 2) + half * 8;
                float2 v = make_float2(acc[mi][ni][half*2] + b0v, acc[mi][ni][half*2+1] + b1v);
                *(float2*)(out + (size_t)m * EMB + n) = v;
            }
        }
    }
}

// V[bh][l][d] -> Vt[bh][d][l] (hi and lo)
__global__ void __launch_bounds__(256) transpose_v() {
    __shared__ bf16 t[64][66];
    const int bh = blockIdx.y, l0 = blockIdx.x * 64;
    #pragma unroll
    for (int a = 0; a < 2; ++a) {
        const bf16* src = (a ? g_Vl : g_Vh) + ((size_t)bh * LSEQ + l0) * HDIM;
        bf16* dst = (a ? g_Vtl : g_Vth) + (size_t)bh * HDIM * LSEQ;
        __syncthreads();
        for (int u = threadIdx.x; u < 64 * 32; u += 256) {
            int r = u >> 5, cu = u & 31;
            bf162 w = *(const bf162*)(src + (size_t)r * HDIM + cu * 2);
            t[r][cu * 2] = w.x; t[r][cu * 2 + 1] = w.y;
        }
        __syncthreads();
        for (int u = threadIdx.x; u < 64 * 32; u += 256) {
            int d = u >> 5, cl = u & 31;
            bf162 o;
            o.x = t[cl * 2][d]; o.y = t[cl * 2 + 1][d];
            *(bf162*)(dst + (size_t)d * LSEQ + l0 + cl * 2) = o;
        }
    }
}

// ---------------- fused flash attention ----------------
// 512 thr, 16 warps x 16 q-rows = 256 q-rows per CTA.
// smem: Qh@0 (32K), Ql@32K, stages@64K + (t&1)*32K {Kh,Kl,Vth,Vtl 8K each}, mask@128K (2x64 f32)
#define NT (LSEQ/64)
__device__ __forceinline__ void attn_prefetch(uint32_t sb, int t,
    const bf16* Kh, const bf16* Kl, const bf16* Vh, const bf16* Vl)
{
    const int tid = threadIdx.x;
    const int s0 = t * 64;
    const uint32_t b0 = sb + 65536u + (uint32_t)(t & 1) * 32768u;
    #pragma unroll
    for (int it = 0; it < 4; ++it) {
        int u = it * 512 + tid;
        int op = u >> 9, idx = u & 511;
        int row = idx >> 3, c = idx & 7;
        uint32_t off = (uint32_t)(row * 128 + c * 16);
        const void* s;
        if (op == 0)      s = Kh + (size_t)(s0 + row) * HDIM + c * 8;
        else if (op == 1) s = Kl + (size_t)(s0 + row) * HDIM + c * 8;
        else if (op == 2) s = Vh + (size_t)row * LSEQ + s0 + c * 8;
        else              s = Vl + (size_t)row * LSEQ + s0 + c * 8;
        CPA16(b0 + (uint32_t)op * 8192u + SW128(off), s);
    }
    CPCOMMIT();
}

__global__ void __launch_bounds__(512) attn_mma(const unsigned char* __restrict__ mask) {
    extern __shared__ char sm[];
    uint32_t sb = smem_u32(sm);
    float* smb = (float*)(sm + 131072);   // [2][64]
    const int tid = threadIdx.x, lane = tid & 31, wid = tid >> 5;
    const int q0 = blockIdx.x * 256, bh = blockIdx.y, b = bh >> 4, h = bh & 15;
    const bf16* Qhp = g_Qh + ((size_t)bh * LSEQ + q0) * HDIM;
    const bf16* Qlp = g_Ql + ((size_t)bh * LSEQ + q0) * HDIM;
    const bf16* Khp = g_Kh + (size_t)bh * LSEQ * HDIM;
    const bf16* Klp = g_Kl + (size_t)bh * LSEQ * HDIM;
    const bf16* Vhp = g_Vth + (size_t)bh * HDIM * LSEQ;
    const bf16* Vlp = g_Vtl + (size_t)bh * HDIM * LSEQ;

    // Q tiles (256 rows x 64, hi/lo) + stage 0
    #pragma unroll
    for (int it = 0; it < 8; ++it) {
        int u = it * 512 + tid;
        const bf16* src = (u < 2048) ? Qhp : Qlp;
        int idx = u & 2047;
        int row = idx >> 3, c = idx & 7;
        uint32_t off = (uint32_t)(row * 128 + c * 16);
        CPA16(sb + (u < 2048 ? 0u : 32768u) + SW128(off), src + (size_t)row * HDIM + c * 8);
    }
    CPCOMMIT();
    attn_prefetch(sb, 0, Khp, Klp, Vhp, Vlp);
    if (tid < 64) smb[tid] = mask[(size_t)tid * BATCH + b] ? -1e30f : 0.0f;

    float m0s = -1e30f, m1s = -1e30f, l0s = 0.f, l1s = 0.f;
    float o[8][4] = {};

    const int arow = lane & 15;
    const uint32_t acolh = (uint32_t)((lane >> 4) * 16);
    const int brow = (lane & 7) + ((lane >> 4) << 3);
    const uint32_t bcolh = (uint32_t)(((lane >> 3) & 1) * 16);

    for (int t = 0; t < NT; ++t) {
        CPWAIT(0);
        __syncthreads();
        if (t + 1 < NT) {
            attn_prefetch(sb, t + 1, Khp, Klp, Vhp, Vlp);
            if (tid < 64)
                smb[((t + 1) & 1) * 64 + tid] =
                    mask[(size_t)((t + 1) * 64 + tid) * BATCH + b] ? -1e30f : 0.0f;
        }
        const float* smbt = smb + (t & 1) * 64;
        const uint32_t kb = sb + 65536u + (uint32_t)(t & 1) * 32768u;

        // S = Q K^T  (16 rows x 64 keys per warp); Q frags reloaded per s-iter
        float sacc[8][4] = {};
        #pragma unroll
        for (int s = 0; s < 4; ++s) {
            uint32_t qhs[4], qls[4];
            {
                uint32_t off = (uint32_t)((wid * 16 + arow) * 128 + s * 32) + acolh;
                uint32_t sw = SW128(off);
                LDSM4(qhs[0], qhs[1], qhs[2], qhs[3], sb + sw);
                LDSM4(qls[0], qls[1], qls[2], qls[3], sb + 32768u + sw);
            }
            uint32_t kh[8][2], kl[8][2];
            #pragma unroll
            for (int p = 0; p < 4; ++p) {
                uint32_t off = (uint32_t)((p * 16 + brow) * 128 + s * 32) + bcolh;
                uint32_t sw = SW128(off);
                LDSM4(kh[2*p][0], kh[2*p][1], kh[2*p+1][0], kh[2*p+1][1], kb + sw);
                LDSM4(kl[2*p][0], kl[2*p][1], kl[2*p+1][0], kl[2*p+1][1], kb + 8192u + sw);
            }
            #pragma unroll
            for (int ni = 0; ni < 8; ++ni) {
                MMA16(sacc[ni], qhs, kh[ni]);
                MMA16(sacc[ni], qhs, kl[ni]);
                MMA16(sacc[ni], qls, kh[ni]);
            }
        }

        // mask + online softmax (rows r0 = lane>>2, r0+8)
        float mx0 = -1e30f, mx1 = -1e30f;
        #pragma unroll
        for (int ni = 0; ni < 8; ++ni) {
            float mb0 = smbt[ni * 8 + (lane & 3) * 2];
            float mb1 = smbt[ni * 8 + (lane & 3) * 2 + 1];
            sacc[ni][0] += mb0; sacc[ni][1] += mb1;
            sacc[ni][2] += mb0; sacc[ni][3] += mb1;
            mx0 = fmaxf(mx0, fmaxf(sacc[ni][0], sacc[ni][1]));
            mx1 = fmaxf(mx1, fmaxf(sacc[ni][2], sacc[ni][3]));
        }
        mx0 = fmaxf(mx0, __shfl_xor_sync(0xffffffffu, mx0, 1));
        mx0 = fmaxf(mx0, __shfl_xor_sync(0xffffffffu, mx0, 2));
        mx1 = fmaxf(mx1, __shfl_xor_sync(0xffffffffu, mx1, 1));
        mx1 = fmaxf(mx1, __shfl_xor_sync(0xffffffffu, mx1, 2));
        float mn0 = fmaxf(m0s, mx0), mn1 = fmaxf(m1s, mx1);
        float al0 = __expf(m0s - mn0), al1 = __expf(m1s - mn1);
        float su0 = 0.f, su1 = 0.f;
        #pragma unroll
        for (int ni = 0; ni < 8; ++ni) {
            sacc[ni][0] = __expf(sacc[ni][0] - mn0);
            sacc[ni][1] = __expf(sacc[ni][1] - mn0);
            sacc[ni][2] = __expf(sacc[ni][2] - mn1);
            sacc[ni][3] = __expf(sacc[ni][3] - mn1);
            su0 += sacc[ni][0] + sacc[ni][1];
            su1 += sacc[ni][2] + sacc[ni][3];
        }
        su0 += __shfl_xor_sync(0xffffffffu, su0, 1);
        su0 += __shfl_xor_sync(0xffffffffu, su0, 2);
        su1 += __shfl_xor_sync(0xffffffffu, su1, 1);
        su1 += __shfl_xor_sync(0xffffffffu, su1, 2);
        m0s = mn0; m1s = mn1;
        l0s = l0s * al0 + su0; l1s = l1s * al1 + su1;
        #pragma unroll
        for (int di = 0; di < 8; ++di) {
            o[di][0] *= al0; o[di][1] *= al0;
            o[di][2] *= al1; o[di][3] *= al1;
        }

        // O += P V  (P from sacc via C->A frag identity, split hi/lo)
        #pragma unroll
        for (int s = 0; s < 4; ++s) {
            uint32_t ph[4], pl[4];
            packsplit(sacc[2*s][0],   sacc[2*s][1],   ph[0], pl[0]);
            packsplit(sacc[2*s][2],   sacc[2*s][3],   ph[1], pl[1]);
            packsplit(sacc[2*s+1][0], sacc[2*s+1][1], ph[2], pl[2]);
            packsplit(sacc[2*s+1][2], sacc[2*s+1][3], ph[3], pl[3]);
            uint32_t vh[8][2], vl[8][2];
            #pragma unroll
            for (int p = 0; p < 4; ++p) {
                uint32_t off = (uint32_t)((p * 16 + brow) * 128 + s * 32) + bcolh;
                uint32_t sw = SW128(off);
                LDSM4(vh[2*p][0], vh[2*p][1], vh[2*p+1][0], vh[2*p+1][1], kb + 16384u + sw);
                LDSM4(vl[2*p][0], vl[2*p][1], vl[2*p+1][0], vl[2*p+1][1], kb + 24576u + sw);
            }
            #pragma unroll
            for (int di = 0; di < 8; ++di) {
                MMA16(o[di], ph, vh[di]);
                MMA16(o[di], pl, vh[di]);
                MMA16(o[di], ph, vl[di]);
            }
        }
    }

    // normalize + write ctx (hi/lo split, token-major)
    float inv0 = 1.f / l0s, inv1 = 1.f / l1s;
    int r0 = q0 + wid * 16 + (lane >> 2);
    #pragma unroll
    for (int di = 0; di < 8; ++di) {
        int col = h * 64 + di * 8 + (lane & 3) * 2;
        bf162 hi, lo;
        split2(o[di][0] * inv0, o[di][1] * inv0, hi, lo);
        size_t off0 = (size_t)(r0 * BATCH + b) * EMB + col;
        *(bf162*)(g_Ch + off0) = hi; *(bf162*)(g_Cl + off0) = lo;
        split2(o[di][2] * inv1, o[di][3] * inv1, hi, lo);
        size_t off1 = (size_t)((r0 + 8) * BATCH + b) * EMB + col;
        *(bf162*)(g_Ch + off1) = hi; *(bf162*)(g_Cl + off1) = lo;
    }
}

// ---------------- launch ----------------
extern "C" void kernel_launch(void* const* d_in, const int* in_sizes, int n_in,
                              void* d_out, int out_size)
{
    const float* x     = (const float*)d_in[0];
    const float* w_in  = (const float*)d_in[1];
    const float* b_in  = (const float*)d_in[2];
    const float* w_out = (const float*)d_in[3];
    const float* b_out = (const float*)d_in[4];
    const unsigned char* mask = (const unsigned char*)d_in[5];
    float* out = (float*)d_out;

    constexpr int SMEM_PROJ = 3 * 49152;       // 3 stages x 48KB = 144KB
    constexpr int SMEM_ATTN = 131072 + 512;    // Q 64K + 2 stages x 32K + mask
    cudaFuncSetAttribute(qkv_mma,  cudaFuncAttributeMaxDynamicSharedMemorySize, SMEM_PROJ);
    cudaFuncSetAttribute(out_mma,  cudaFuncAttributeMaxDynamicSharedMemorySize, SMEM_PROJ);
    cudaFuncSetAttribute(attn_mma, cudaFuncAttributeMaxDynamicSharedMemorySize, SMEM_ATTN);

    bf16 *xh, *xl, *wih, *wil, *woh, *wol;
    cudaGetSymbolAddress((void**)&xh,  g_xh);  cudaGetSymbolAddress((void**)&xl,  g_xl);
    cudaGetSymbolAddress((void**)&wih, g_wih); cudaGetSymbolAddress((void**)&wil, g_wil);
    cudaGetSymbolAddress((void**)&woh, g_woh); cudaGetSymbolAddress((void**)&wol, g_wol);

    split_fp32<<<(MTOK*EMB/4 + 255)/256, 256>>>(x,     xh,  xl,  MTOK*EMB/4);
    split_fp32<<<(NQKV*EMB/4 + 255)/256, 256>>>(w_in,  wih, wil, NQKV*EMB/4);
    split_fp32<<<(EMB*EMB/4  + 255)/256, 256>>>(w_out, woh, wol, EMB*EMB/4);

    qkv_mma<<<dim3(NQKV/256, MTOK/128), 512, SMEM_PROJ>>>(b_in);
    transpose_v<<<dim3(LSEQ/64, BHN), 256>>>();
    attn_mma<<<dim3(LSEQ/256, BHN), 512, SMEM_ATTN>>>(mask);
    out_mma<<<dim3(EMB/256, MTOK/128), 512, SMEM_PROJ>>>(b_out, out);
}

// round 12
// speedup vs baseline: 4.2020x; 1.2450x over previous
#include <cuda_runtime.h>
#include <cuda_bf16.h>
#include <cuda_fp16.h>
#include <math.h>
#include <cstdint>

#define LSEQ 2048
#define BATCH 4
#define EMB 1024
#define HEADS 16
#define HDIM 64
#define MTOK 8192
#define NQKV 3072
#define BHN (BATCH*HEADS)

typedef __nv_bfloat16 bf16;
typedef __nv_bfloat162 bf162;

// ---------------- device scratch (allocation-free) ----------------
__device__ __align__(256) bf16 g_xh[(size_t)MTOK*EMB],  g_xl[(size_t)MTOK*EMB];
__device__ __align__(256) bf16 g_wih[(size_t)NQKV*EMB], g_wil[(size_t)NQKV*EMB];
__device__ __align__(256) bf16 g_woh[(size_t)EMB*EMB],  g_wol[(size_t)EMB*EMB];
__device__ __align__(256) __half g_Qf[(size_t)BHN*LSEQ*HDIM];
__device__ __align__(256) __half g_Kf[(size_t)BHN*LSEQ*HDIM];
__device__ __align__(256) __half g_Vf[(size_t)BHN*LSEQ*HDIM];
__device__ __align__(256) __half g_Vtf[(size_t)BHN*HDIM*LSEQ];
__device__ __align__(256) bf16 g_Ch[(size_t)MTOK*EMB], g_Cl[(size_t)MTOK*EMB];

// ---------------- helpers ----------------
__device__ __forceinline__ uint32_t smem_u32(const void* p) {
    uint32_t a;
    asm("{ .reg .u64 t; cvta.to.shared.u64 t, %1; cvt.u32.u64 %0, t; }" : "=r"(a) : "l"(p));
    return a;
}
#define CPA16(dst, src) asm volatile("cp.async.cg.shared.global [%0], [%1], 16;" :: "r"(dst), "l"(src))
#define CPCOMMIT()      asm volatile("cp.async.commit_group;")
#define CPWAIT(n)       asm volatile("cp.async.wait_group %0;" :: "n"(n))
#define LDSM4(r0,r1,r2,r3,a) \
    asm volatile("ldmatrix.sync.aligned.m8n8.x4.shared.b16 {%0,%1,%2,%3}, [%4];" \
        : "=r"(r0),"=r"(r1),"=r"(r2),"=r"(r3) : "r"(a))
#define MMA16(d,a,b) \
    asm volatile("mma.sync.aligned.m16n8k16.row.col.f32.bf16.bf16.f32 " \
        "{%0,%1,%2,%3},{%4,%5,%6,%7},{%8,%9},{%0,%1,%2,%3};" \
        : "+f"((d)[0]),"+f"((d)[1]),"+f"((d)[2]),"+f"((d)[3]) \
        : "r"((a)[0]),"r"((a)[1]),"r"((a)[2]),"r"((a)[3]),"r"((b)[0]),"r"((b)[1]))
#define MMA16H(d,a,b) \
    asm volatile("mma.sync.aligned.m16n8k16.row.col.f32.f16.f16.f32 " \
        "{%0,%1,%2,%3},{%4,%5,%6,%7},{%8,%9},{%0,%1,%2,%3};" \
        : "+f"((d)[0]),"+f"((d)[1]),"+f"((d)[2]),"+f"((d)[3]) \
        : "r"((a)[0]),"r"((a)[1]),"r"((a)[2]),"r"((a)[3]),"r"((b)[0]),"r"((b)[1]))
#define SW64(o)  ((o) ^ (((o)>>3)&0x30))
#define SW128(o) ((o) ^ (((o)>>3)&0x70))

__device__ __forceinline__ void split2(float x, float y, bf162& hi, bf162& lo) {
    hi.x = __float2bfloat16_rn(x); hi.y = __float2bfloat16_rn(y);
    lo.x = __float2bfloat16_rn(x - __bfloat162float(hi.x));
    lo.y = __float2bfloat16_rn(y - __bfloat162float(hi.y));
}
// fp16 split of a float pair into hi/lo packed half2 (for P in PV)
__device__ __forceinline__ void packsplit_h(float x, float y, uint32_t& hi, uint32_t& lo) {
    __half2 h = __floats2half2_rn(x, y);
    float rx = x - __half2float(__low2half(h));
    float ry = y - __half2float(__high2half(h));
    __half2 l = __floats2half2_rn(rx, ry);
    hi = *(uint32_t*)&h; lo = *(uint32_t*)&l;
}

// ---------------- projection GEMM core (C = A·B^T, 3-term bf16 split) ----------
// block 128x256, 512 thr (16 warps 2x8, warp tile 64x32), K-chunks of 32,
// 3-stage cp.async ring. stage (48KB): Ah@0 (8K), Al@8K, Bh@16K (16K), Bl@32K; SW64.
#define PSTAGE 49152u
__device__ __forceinline__ void proj_prefetch(uint32_t sbase, int ch,
    const bf16* Ah, const bf16* Al, const bf16* Bh, const bf16* Bl, int lda, int ldb)
{
    const int tid = threadIdx.x;
    const uint32_t b0 = sbase + (uint32_t)(ch % 3) * PSTAGE;
    #pragma unroll
    for (int it = 0; it < 6; ++it) {
        int u = it * 512 + tid;
        const bf16* src; uint32_t roff; int a, ld;
        if (u < 1024) {
            src = (u < 512) ? Ah : Al; roff = (u < 512) ? 0u : 8192u;
            a = u & 511; ld = lda;
        } else {
            a = u - 1024;
            src = (a < 1024) ? Bh : Bl; roff = (a < 1024) ? 16384u : 32768u;
            a &= 1023; ld = ldb;
        }
        int row = a >> 2, c = u & 3;
        const void* s = src + (size_t)row * ld + ch * 32 + c * 8;
        uint32_t off = (uint32_t)(row * 64 + c * 16);
        CPA16(b0 + roff + SW64(off), s);
    }
    CPCOMMIT();
}

__device__ __forceinline__ void proj_core(const bf16* Ah, const bf16* Al,
    const bf16* Bh, const bf16* Bl, int lda, int ldb, int nch,
    uint32_t sbase, float acc[4][4][4])
{
    const int tid = threadIdx.x, lane = tid & 31, wid = tid >> 5;
    const int wm = wid >> 3, wn = wid & 7;
    const int arow = lane & 15;
    const uint32_t acolh = (uint32_t)((lane >> 4) * 16);
    const int brow = (lane & 7) + ((lane >> 4) << 3);
    const uint32_t bcolh = (uint32_t)(((lane >> 3) & 1) * 16);

    proj_prefetch(sbase, 0, Ah, Al, Bh, Bl, lda, ldb);
    proj_prefetch(sbase, 1, Ah, Al, Bh, Bl, lda, ldb);
    for (int ch = 0; ch < nch; ++ch) {
        if (ch + 1 < nch) CPWAIT(1); else CPWAIT(0);
        __syncthreads();
        if (ch + 2 < nch) proj_prefetch(sbase, ch + 2, Ah, Al, Bh, Bl, lda, ldb);
        const uint32_t b0 = sbase + (uint32_t)(ch % 3) * PSTAGE;
        #pragma unroll
        for (int s = 0; s < 2; ++s) {
            uint32_t ah[4][4], al[4][4], bh[4][2], bl[4][2];
            #pragma unroll
            for (int mi = 0; mi < 4; ++mi) {
                uint32_t off = (uint32_t)((wm * 64 + mi * 16 + arow) * 64 + s * 32) + acolh;
                uint32_t sw = SW64(off);
                LDSM4(ah[mi][0], ah[mi][1], ah[mi][2], ah[mi][3], b0 + sw);
                LDSM4(al[mi][0], al[mi][1], al[mi][2], al[mi][3], b0 + 8192u + sw);
            }
            #pragma unroll
            for (int p = 0; p < 2; ++p) {
                uint32_t off = (uint32_t)((wn * 32 + p * 16 + brow) * 64 + s * 32) + bcolh;
                uint32_t sw = SW64(off);
                LDSM4(bh[2*p][0], bh[2*p][1], bh[2*p+1][0], bh[2*p+1][1], b0 + 16384u + sw);
                LDSM4(bl[2*p][0], bl[2*p][1], bl[2*p+1][0], bl[2*p+1][1], b0 + 32768u + sw);
            }
            #pragma unroll
            for (int mi = 0; mi < 4; ++mi)
                #pragma unroll
                for (int ni = 0; ni < 4; ++ni) {
                    MMA16(acc[mi][ni], ah[mi], bh[ni]);
                    MMA16(acc[mi][ni], ah[mi], bl[ni]);
                    MMA16(acc[mi][ni], al[mi], bh[ni]);
                }
        }
    }
}

// ---------------- kernels ----------------
__global__ void __launch_bounds__(256) split_fp32(const float* __restrict__ src,
                                                  bf16* __restrict__ hi,
                                                  bf16* __restrict__ lo, int n4) {
    int i = blockIdx.x * 256 + threadIdx.x;
    if (i >= n4) return;
    float4 v = ((const float4*)src)[i];
    bf162 h0, l0, h1, l1;
    split2(v.x, v.y, h0, l0);
    split2(v.z, v.w, h1, l1);
    ((bf162*)hi)[2*i] = h0; ((bf162*)hi)[2*i+1] = h1;
    ((bf162*)lo)[2*i] = l0; ((bf162*)lo)[2*i+1] = l1;
}

__global__ void __launch_bounds__(512) qkv_mma(const float* __restrict__ bias) {
    extern __shared__ char sm[];
    uint32_t sb = smem_u32(sm);
    const int m0 = blockIdx.y * 128, n0 = blockIdx.x * 256;
    float acc[4][4][4] = {};
    proj_core(g_xh + (size_t)m0 * EMB, g_xl + (size_t)m0 * EMB,
              g_wih + (size_t)n0 * EMB, g_wil + (size_t)n0 * EMB, EMB, EMB, 32, sb, acc);
    const int lane = threadIdx.x & 31, wid = threadIdx.x >> 5;
    const int wm = wid >> 3, wn = wid & 7;
    #pragma unroll
    for (int mi = 0; mi < 4; ++mi) {
        #pragma unroll
        for (int ni = 0; ni < 4; ++ni) {
            int n = n0 + wn * 32 + ni * 8 + (lane & 3) * 2;
            const int sec = n >> 10;
            __half* dst = sec == 0 ? g_Qf : sec == 1 ? g_Kf : g_Vf;
            const float scale = sec == 0 ? 0.125f : 1.0f;
            int h = (n & 1023) >> 6, dd = n & 63;
            float b0v = bias[n], b1v = bias[n + 1];
            #pragma unroll
            for (int half_ = 0; half_ < 2; ++half_) {
                int m = m0 + wm * 64 + mi * 16 + (lane >> 2) + half_ * 8;
                int l = m >> 2, bb = m & 3;
                float v0 = (acc[mi][ni][half_*2]     + b0v) * scale;
                float v1 = (acc[mi][ni][half_*2 + 1] + b1v) * scale;
                __half2 hv = __floats2half2_rn(v0, v1);
                size_t off = (((size_t)(bb * HEADS + h)) * LSEQ + l) * HDIM + dd;
                *(__half2*)(dst + off) = hv;
            }
        }
    }
}

__global__ void __launch_bounds__(512) out_mma(const float* __restrict__ bias,
                                               float* __restrict__ out) {
    extern __shared__ char sm[];
    uint32_t sb = smem_u32(sm);
    const int m0 = blockIdx.y * 128, n0 = blockIdx.x * 256;
    float acc[4][4][4] = {};
    proj_core(g_Ch + (size_t)m0 * EMB, g_Cl + (size_t)m0 * EMB,
              g_woh + (size_t)n0 * EMB, g_wol + (size_t)n0 * EMB, EMB, EMB, 32, sb, acc);
    const int lane = threadIdx.x & 31, wid = threadIdx.x >> 5;
    const int wm = wid >> 3, wn = wid & 7;
    #pragma unroll
    for (int mi = 0; mi < 4; ++mi) {
        #pragma unroll
        for (int ni = 0; ni < 4; ++ni) {
            int n = n0 + wn * 32 + ni * 8 + (lane & 3) * 2;
            float b0v = bias[n], b1v = bias[n + 1];
            #pragma unroll
            for (int half_ = 0; half_ < 2; ++half_) {
                int m = m0 + wm * 64 + mi * 16 + (lane >> 2) + half_ * 8;
                float2 v = make_float2(acc[mi][ni][half_*2] + b0v, acc[mi][ni][half_*2+1] + b1v);
                *(float2*)(out + (size_t)m * EMB + n) = v;
            }
        }
    }
}

// V[bh][l][d] -> Vt[bh][d][l] (fp16)
__global__ void __launch_bounds__(256) transpose_v() {
    __shared__ __half t[64][66];
    const int bh = blockIdx.y, l0 = blockIdx.x * 64;
    const __half* src = g_Vf + ((size_t)bh * LSEQ + l0) * HDIM;
    __half* dst = g_Vtf + (size_t)bh * HDIM * LSEQ;
    for (int u = threadIdx.x; u < 64 * 32; u += 256) {
        int r = u >> 5, cu = u & 31;
        __half2 w = *(const __half2*)(src + (size_t)r * HDIM + cu * 2);
        t[r][cu * 2] = __low2half(w); t[r][cu * 2 + 1] = __high2half(w);
    }
    __syncthreads();
    for (int u = threadIdx.x; u < 64 * 32; u += 256) {
        int d = u >> 5, cl = u & 31;
        __half2 o = __halves2half2(t[cl * 2][d], t[cl * 2 + 1][d]);
        *(__half2*)(dst + (size_t)d * LSEQ + l0 + cl * 2) = o;
    }
}

// ---------------- fused flash attention (fp16, 1-term QK + 2-term PV) --------
// 512 thr, 16 warps x 16 q-rows = 256 q-rows per CTA.
// smem: Q@0 (32K fp16), stages@32K + (t&1)*16K {K 8K, Vt 8K}, mask@64K (2x64 f32)
#define NT (LSEQ/64)
__device__ __forceinline__ void attn_prefetch(uint32_t sb, int t,
    const __half* Kp, const __half* Vp)
{
    const int tid = threadIdx.x;
    const int s0 = t * 64;
    const uint32_t b0 = sb + 32768u + (uint32_t)(t & 1) * 16384u;
    #pragma unroll
    for (int it = 0; it < 2; ++it) {
        int u = it * 512 + tid;
        int op = u >> 9, idx = u & 511;
        int row = idx >> 3, c = idx & 7;
        uint32_t off = (uint32_t)(row * 128 + c * 16);
        const void* s = op ? (const void*)(Vp + (size_t)row * LSEQ + s0 + c * 8)
                           : (const void*)(Kp + (size_t)(s0 + row) * HDIM + c * 8);
        CPA16(b0 + (uint32_t)op * 8192u + SW128(off), s);
    }
    CPCOMMIT();
}

__global__ void __launch_bounds__(512) attn_mma(const unsigned char* __restrict__ mask) {
    extern __shared__ char sm[];
    uint32_t sb = smem_u32(sm);
    float* smb = (float*)(sm + 65536);   // [2][64]
    const int tid = threadIdx.x, lane = tid & 31, wid = tid >> 5;
    const int q0 = blockIdx.x * 256, bh = blockIdx.y, b = bh >> 4, h = bh & 15;
    const __half* Qp = g_Qf + ((size_t)bh * LSEQ + q0) * HDIM;
    const __half* Kp = g_Kf + (size_t)bh * LSEQ * HDIM;
    const __half* Vp = g_Vtf + (size_t)bh * HDIM * LSEQ;

    // Q tile (256 rows x 64 fp16) + stage 0
    #pragma unroll
    for (int it = 0; it < 4; ++it) {
        int u = it * 512 + tid;
        int row = u >> 3, c = u & 7;
        uint32_t off = (uint32_t)(row * 128 + c * 16);
        CPA16(sb + SW128(off), Qp + (size_t)row * HDIM + c * 8);
    }
    CPCOMMIT();
    attn_prefetch(sb, 0, Kp, Vp);
    if (tid < 64) smb[tid] = mask[(size_t)tid * BATCH + b] ? -1e30f : 0.0f;

    float m0s = -1e30f, m1s = -1e30f, l0s = 0.f, l1s = 0.f;
    float o[8][4] = {};

    const int arow = lane & 15;
    const uint32_t acolh = (uint32_t)((lane >> 4) * 16);
    const int brow = (lane & 7) + ((lane >> 4) << 3);
    const uint32_t bcolh = (uint32_t)(((lane >> 3) & 1) * 16);

    for (int t = 0; t < NT; ++t) {
        CPWAIT(0);
        __syncthreads();
        if (t + 1 < NT) {
            attn_prefetch(sb, t + 1, Kp, Vp);
            if (tid < 64)
                smb[((t + 1) & 1) * 64 + tid] =
                    mask[(size_t)((t + 1) * 64 + tid) * BATCH + b] ? -1e30f : 0.0f;
        }
        const float* smbt = smb + (t & 1) * 64;
        const uint32_t kb = sb + 32768u + (uint32_t)(t & 1) * 16384u;

        // S = Q K^T  (16 rows x 64 keys per warp), single fp16 pass
        float sacc[8][4] = {};
        #pragma unroll
        for (int s = 0; s < 4; ++s) {
            uint32_t qf[4];
            {
                uint32_t off = (uint32_t)((wid * 16 + arow) * 128 + s * 32) + acolh;
                LDSM4(qf[0], qf[1], qf[2], qf[3], sb + SW128(off));
            }
            uint32_t kf[8][2];
            #pragma unroll
            for (int p = 0; p < 4; ++p) {
                uint32_t off = (uint32_t)((p * 16 + brow) * 128 + s * 32) + bcolh;
                uint32_t sw = SW128(off);
                LDSM4(kf[2*p][0], kf[2*p][1], kf[2*p+1][0], kf[2*p+1][1], kb + sw);
            }
            #pragma unroll
            for (int ni = 0; ni < 8; ++ni) MMA16H(sacc[ni], qf, kf[ni]);
        }

        // mask + online softmax (rows r0 = lane>>2, r0+8)
        float mx0 = -1e30f, mx1 = -1e30f;
        #pragma unroll
        for (int ni = 0; ni < 8; ++ni) {
            float mb0 = smbt[ni * 8 + (lane & 3) * 2];
            float mb1 = smbt[ni * 8 + (lane & 3) * 2 + 1];
            sacc[ni][0] += mb0; sacc[ni][1] += mb1;
            sacc[ni][2] += mb0; sacc[ni][3] += mb1;
            mx0 = fmaxf(mx0, fmaxf(sacc[ni][0], sacc[ni][1]));
            mx1 = fmaxf(mx1, fmaxf(sacc[ni][2], sacc[ni][3]));
        }
        mx0 = fmaxf(mx0, __shfl_xor_sync(0xffffffffu, mx0, 1));
        mx0 = fmaxf(mx0, __shfl_xor_sync(0xffffffffu, mx0, 2));
        mx1 = fmaxf(mx1, __shfl_xor_sync(0xffffffffu, mx1, 1));
        mx1 = fmaxf(mx1, __shfl_xor_sync(0xffffffffu, mx1, 2));
        float mn0 = fmaxf(m0s, mx0), mn1 = fmaxf(m1s, mx1);
        float al0 = __expf(m0s - mn0), al1 = __expf(m1s - mn1);
        float su0 = 0.f, su1 = 0.f;
        #pragma unroll
        for (int ni = 0; ni < 8; ++ni) {
            sacc[ni][0] = __expf(sacc[ni][0] - mn0);
            sacc[ni][1] = __expf(sacc[ni][1] - mn0);
            sacc[ni][2] = __expf(sacc[ni][2] - mn1);
            sacc[ni][3] = __expf(sacc[ni][3] - mn1);
            su0 += sacc[ni][0] + sacc[ni][1];
            su1 += sacc[ni][2] + sacc[ni][3];
        }
        su0 += __shfl_xor_sync(0xffffffffu, su0, 1);
        su0 += __shfl_xor_sync(0xffffffffu, su0, 2);
        su1 += __shfl_xor_sync(0xffffffffu, su1, 1);
        su1 += __shfl_xor_sync(0xffffffffu, su1, 2);
        m0s = mn0; m1s = mn1;
        l0s = l0s * al0 + su0; l1s = l1s * al1 + su1;
        #pragma unroll
        for (int di = 0; di < 8; ++di) {
            o[di][0] *= al0; o[di][1] *= al0;
            o[di][2] *= al1; o[di][3] *= al1;
        }

        // O += P V : P split hi/lo in fp16 (2 passes), V single fp16
        #pragma unroll
        for (int s = 0; s < 4; ++s) {
            uint32_t ph[4], pl[4];
            packsplit_h(sacc[2*s][0],   sacc[2*s][1],   ph[0], pl[0]);
            packsplit_h(sacc[2*s][2],   sacc[2*s][3],   ph[1], pl[1]);
            packsplit_h(sacc[2*s+1][0], sacc[2*s+1][1], ph[2], pl[2]);
            packsplit_h(sacc[2*s+1][2], sacc[2*s+1][3], ph[3], pl[3]);
            uint32_t vf[8][2];
            #pragma unroll
            for (int p = 0; p < 4; ++p) {
                uint32_t off = (uint32_t)((p * 16 + brow) * 128 + s * 32) + bcolh;
                uint32_t sw = SW128(off);
                LDSM4(vf[2*p][0], vf[2*p][1], vf[2*p+1][0], vf[2*p+1][1], kb + 8192u + sw);
            }
            #pragma unroll
            for (int di = 0; di < 8; ++di) {
                MMA16H(o[di], ph, vf[di]);
                MMA16H(o[di], pl, vf[di]);
            }
        }
    }

    // normalize + write ctx (bf16 hi/lo split, token-major)
    float inv0 = 1.f / l0s, inv1 = 1.f / l1s;
    int r0 = q0 + wid * 16 + (lane >> 2);
    #pragma unroll
    for (int di = 0; di < 8; ++di) {
        int col = h * 64 + di * 8 + (lane & 3) * 2;
        bf162 hi, lo;
        split2(o[di][0] * inv0, o[di][1] * inv0, hi, lo);
        size_t off0 = (size_t)(r0 * BATCH + b) * EMB + col;
        *(bf162*)(g_Ch + off0) = hi; *(bf162*)(g_Cl + off0) = lo;
        split2(o[di][2] * inv1, o[di][3] * inv1, hi, lo);
        size_t off1 = (size_t)((r0 + 8) * BATCH + b) * EMB + col;
        *(bf162*)(g_Ch + off1) = hi; *(bf162*)(g_Cl + off1) = lo;
    }
}

// ---------------- launch ----------------
extern "C" void kernel_launch(void* const* d_in, const int* in_sizes, int n_in,
                              void* d_out, int out_size)
{
    const float* x     = (const float*)d_in[0];
    const float* w_in  = (const float*)d_in[1];
    const float* b_in  = (const float*)d_in[2];
    const float* w_out = (const float*)d_in[3];
    const float* b_out = (const float*)d_in[4];
    const unsigned char* mask = (const unsigned char*)d_in[5];
    float* out = (float*)d_out;

    constexpr int SMEM_PROJ = 3 * 49152;       // 3 stages x 48KB = 144KB
    constexpr int SMEM_ATTN = 65536 + 512;     // Q 32K + 2 stages x 16K + mask
    cudaFuncSetAttribute(qkv_mma,  cudaFuncAttributeMaxDynamicSharedMemorySize, SMEM_PROJ);
    cudaFuncSetAttribute(out_mma,  cudaFuncAttributeMaxDynamicSharedMemorySize, SMEM_PROJ);
    cudaFuncSetAttribute(attn_mma, cudaFuncAttributeMaxDynamicSharedMemorySize, SMEM_ATTN);

    bf16 *xh, *xl, *wih, *wil, *woh, *wol;
    cudaGetSymbolAddress((void**)&xh,  g_xh);  cudaGetSymbolAddress((void**)&xl,  g_xl);
    cudaGetSymbolAddress((void**)&wih, g_wih); cudaGetSymbolAddress((void**)&wil, g_wil);
    cudaGetSymbolAddress((void**)&woh, g_woh); cudaGetSymbolAddress((void**)&wol, g_wol);

    split_fp32<<<(MTOK*EMB/4 + 255)/256, 256>>>(x,     xh,  xl,  MTOK*EMB/4);
    split_fp32<<<(NQKV*EMB/4 + 255)/256, 256>>>(w_in,  wih, wil, NQKV*EMB/4);
    split_fp32<<<(EMB*EMB/4  + 255)/256, 256>>>(w_out, woh, wol, EMB*EMB/4);

    qkv_mma<<<dim3(NQKV/256, MTOK/128), 512, SMEM_PROJ>>>(b_in);
    transpose_v<<<dim3(LSEQ/64, BHN), 256>>>();
    attn_mma<<<dim3(LSEQ/256, BHN), 512, SMEM_ATTN>>>(mask);
    out_mma<<<dim3(EMB/256, MTOK/128), 512, SMEM_PROJ>>>(b_out, out);
}

// round 14
// speedup vs baseline: 5.0782x; 1.2085x over previous
#include <cuda_runtime.h>
#include <cuda_bf16.h>
#include <cuda_fp16.h>
#include <math.h>
#include <cstdint>

#define LSEQ 2048
#define BATCH 4
#define EMB 1024
#define HEADS 16
#define HDIM 64
#define MTOK 8192
#define NQKV 3072
#define BHN (BATCH*HEADS)

// ---------------- device scratch (allocation-free) ----------------
__device__ __align__(256) __half g_xf[(size_t)MTOK*EMB];
__device__ __align__(256) __half g_wih[(size_t)NQKV*EMB], g_wil[(size_t)NQKV*EMB];
__device__ __align__(256) __half g_woh[(size_t)EMB*EMB],  g_wol[(size_t)EMB*EMB];
__device__ __align__(256) __half g_Qf[(size_t)BHN*LSEQ*HDIM];
__device__ __align__(256) __half g_Kf[(size_t)BHN*LSEQ*HDIM];
__device__ __align__(256) __half g_Vf[(size_t)BHN*LSEQ*HDIM];
__device__ __align__(256) __half g_Vtf[(size_t)BHN*HDIM*LSEQ];
__device__ __align__(256) __half g_Cf[(size_t)MTOK*EMB];

// ---------------- helpers ----------------
__device__ __forceinline__ uint32_t smem_u32(const void* p) {
    uint32_t a;
    asm("{ .reg .u64 t; cvta.to.shared.u64 t, %1; cvt.u32.u64 %0, t; }" : "=r"(a) : "l"(p));
    return a;
}
#define CPA16(dst, src) asm volatile("cp.async.cg.shared.global [%0], [%1], 16;" :: "r"(dst), "l"(src))
#define CPCOMMIT()      asm volatile("cp.async.commit_group;")
#define CPWAIT(n)       asm volatile("cp.async.wait_group %0;" :: "n"(n))
#define LDSM4(r0,r1,r2,r3,a) \
    asm volatile("ldmatrix.sync.aligned.m8n8.x4.shared.b16 {%0,%1,%2,%3}, [%4];" \
        : "=r"(r0),"=r"(r1),"=r"(r2),"=r"(r3) : "r"(a))
#define MMA16H(d,a,b) \
    asm volatile("mma.sync.aligned.m16n8k16.row.col.f32.f16.f16.f32 " \
        "{%0,%1,%2,%3},{%4,%5,%6,%7},{%8,%9},{%0,%1,%2,%3};" \
        : "+f"((d)[0]),"+f"((d)[1]),"+f"((d)[2]),"+f"((d)[3]) \
        : "r"((a)[0]),"r"((a)[1]),"r"((a)[2]),"r"((a)[3]),"r"((b)[0]),"r"((b)[1]))
#define SW64(o)  ((o) ^ (((o)>>3)&0x30))
#define SW128(o) ((o) ^ (((o)>>3)&0x70))

// fp16 split of a float pair into hi/lo packed half2
__device__ __forceinline__ void packsplit_h(float x, float y, uint32_t& hi, uint32_t& lo) {
    __half2 h = __floats2half2_rn(x, y);
    float rx = x - __half2float(__low2half(h));
    float ry = y - __half2float(__high2half(h));
    __half2 l = __floats2half2_rn(rx, ry);
    hi = *(uint32_t*)&h; lo = *(uint32_t*)&l;
}

// ---------------- projection GEMM core (C = A·B^T, 2-term fp16: A·(Bh+Bl)) ---
// block 128x256, 512 thr (16 warps 2x8, warp tile 64x32), K-chunks of 32,
// 3-stage cp.async ring. stage (40KB): A@0 (8K), Bh@8K (16K), Bl@24K (16K); SW64.
#define PSTAGE 40960u
__device__ __forceinline__ void proj_prefetch(uint32_t sbase, int ch,
    const __half* A, const __half* Bh, const __half* Bl, int lda, int ldb)
{
    const int tid = threadIdx.x;
    const uint32_t b0 = sbase + (uint32_t)(ch % 3) * PSTAGE;
    #pragma unroll
    for (int it = 0; it < 5; ++it) {
        int u = it * 512 + tid;
        const __half* src; uint32_t roff; int a, ld;
        if (u < 512) { src = A; roff = 0u; a = u; ld = lda; }
        else {
            int v = u - 512;
            src = (v < 1024) ? Bh : Bl; roff = (v < 1024) ? 8192u : 24576u;
            a = v & 1023; ld = ldb;
        }
        int row = a >> 2, c = a & 3;
        const void* s = src + (size_t)row * ld + ch * 32 + c * 8;
        uint32_t off = (uint32_t)(row * 64 + c * 16);
        CPA16(b0 + roff + SW64(off), s);
    }
    CPCOMMIT();
}

__device__ __forceinline__ void proj_core(const __half* A,
    const __half* Bh, const __half* Bl, int lda, int ldb, int nch,
    uint32_t sbase, float acc[4][4][4])
{
    const int tid = threadIdx.x, lane = tid & 31, wid = tid >> 5;
    const int wm = wid >> 3, wn = wid & 7;
    const int arow = lane & 15;
    const uint32_t acolh = (uint32_t)((lane >> 4) * 16);
    const int brow = (lane & 7) + ((lane >> 4) << 3);
    const uint32_t bcolh = (uint32_t)(((lane >> 3) & 1) * 16);

    proj_prefetch(sbase, 0, A, Bh, Bl, lda, ldb);
    proj_prefetch(sbase, 1, A, Bh, Bl, lda, ldb);
    for (int ch = 0; ch < nch; ++ch) {
        if (ch + 1 < nch) CPWAIT(1); else CPWAIT(0);
        __syncthreads();
        if (ch + 2 < nch) proj_prefetch(sbase, ch + 2, A, Bh, Bl, lda, ldb);
        const uint32_t b0 = sbase + (uint32_t)(ch % 3) * PSTAGE;
        #pragma unroll
        for (int s = 0; s < 2; ++s) {
            uint32_t af[4][4], bh[4][2], bl[4][2];
            #pragma unroll
            for (int mi = 0; mi < 4; ++mi) {
                uint32_t off = (uint32_t)((wm * 64 + mi * 16 + arow) * 64 + s * 32) + acolh;
                LDSM4(af[mi][0], af[mi][1], af[mi][2], af[mi][3], b0 + SW64(off));
            }
            #pragma unroll
            for (int p = 0; p < 2; ++p) {
                uint32_t off = (uint32_t)((wn * 32 + p * 16 + brow) * 64 + s * 32) + bcolh;
                uint32_t sw = SW64(off);
                LDSM4(bh[2*p][0], bh[2*p][1], bh[2*p+1][0], bh[2*p+1][1], b0 + 8192u + sw);
                LDSM4(bl[2*p][0], bl[2*p][1], bl[2*p+1][0], bl[2*p+1][1], b0 + 24576u + sw);
            }
            #pragma unroll
            for (int mi = 0; mi < 4; ++mi)
                #pragma unroll
                for (int ni = 0; ni < 4; ++ni) {
                    MMA16H(acc[mi][ni], af[mi], bh[ni]);
                    MMA16H(acc[mi][ni], af[mi], bl[ni]);
                }
        }
    }
}

// ---------------- conversion kernels ----------------
__global__ void __launch_bounds__(256) tofp16(const float* __restrict__ src,
                                              __half* __restrict__ dst, int n4) {
    int i = blockIdx.x * 256 + threadIdx.x;
    if (i >= n4) return;
    float4 v = ((const float4*)src)[i];
    ((__half2*)dst)[2*i]   = __floats2half2_rn(v.x, v.y);
    ((__half2*)dst)[2*i+1] = __floats2half2_rn(v.z, v.w);
}
__global__ void __launch_bounds__(256) split_f16(const float* __restrict__ src,
                                                 __half* __restrict__ hi,
                                                 __half* __restrict__ lo, int n4) {
    int i = blockIdx.x * 256 + threadIdx.x;
    if (i >= n4) return;
    float4 v = ((const float4*)src)[i];
    uint32_t h0, l0, h1, l1;
    packsplit_h(v.x, v.y, h0, l0);
    packsplit_h(v.z, v.w, h1, l1);
    ((uint32_t*)hi)[2*i] = h0; ((uint32_t*)hi)[2*i+1] = h1;
    ((uint32_t*)lo)[2*i] = l0; ((uint32_t*)lo)[2*i+1] = l1;
}

__global__ void __launch_bounds__(512) qkv_mma(const float* __restrict__ bias) {
    extern __shared__ char sm[];
    uint32_t sb = smem_u32(sm);
    const int m0 = blockIdx.y * 128, n0 = blockIdx.x * 256;
    float acc[4][4][4] = {};
    proj_core(g_xf + (size_t)m0 * EMB,
              g_wih + (size_t)n0 * EMB, g_wil + (size_t)n0 * EMB, EMB, EMB, 32, sb, acc);
    const int lane = threadIdx.x & 31, wid = threadIdx.x >> 5;
    const int wm = wid >> 3, wn = wid & 7;
    #pragma unroll
    for (int mi = 0; mi < 4; ++mi) {
        #pragma unroll
        for (int ni = 0; ni < 4; ++ni) {
            int n = n0 + wn * 32 + ni * 8 + (lane & 3) * 2;
            const int sec = n >> 10;
            __half* dst = sec == 0 ? g_Qf : sec == 1 ? g_Kf : g_Vf;
            const float scale = sec == 0 ? 0.125f : 1.0f;
            int h = (n & 1023) >> 6, dd = n & 63;
            float b0v = bias[n], b1v = bias[n + 1];
            #pragma unroll
            for (int half_ = 0; half_ < 2; ++half_) {
                int m = m0 + wm * 64 + mi * 16 + (lane >> 2) + half_ * 8;
                int l = m >> 2, bb = m & 3;
                float v0 = (acc[mi][ni][half_*2]     + b0v) * scale;
                float v1 = (acc[mi][ni][half_*2 + 1] + b1v) * scale;
                __half2 hv = __floats2half2_rn(v0, v1);
                size_t off = (((size_t)(bb * HEADS + h)) * LSEQ + l) * HDIM + dd;
                *(__half2*)(dst + off) = hv;
            }
        }
    }
}

__global__ void __launch_bounds__(512) out_mma(const float* __restrict__ bias,
                                               float* __restrict__ out) {
    extern __shared__ char sm[];
    uint32_t sb = smem_u32(sm);
    const int m0 = blockIdx.y * 128, n0 = blockIdx.x * 256;
    float acc[4][4][4] = {};
    proj_core(g_Cf + (size_t)m0 * EMB,
              g_woh + (size_t)n0 * EMB, g_wol + (size_t)n0 * EMB, EMB, EMB, 32, sb, acc);
    const int lane = threadIdx.x & 31, wid = threadIdx.x >> 5;
    const int wm = wid >> 3, wn = wid & 7;
    #pragma unroll
    for (int mi = 0; mi < 4; ++mi) {
        #pragma unroll
        for (int ni = 0; ni < 4; ++ni) {
            int n = n0 + wn * 32 + ni * 8 + (lane & 3) * 2;
            float b0v = bias[n], b1v = bias[n + 1];
            #pragma unroll
            for (int half_ = 0; half_ < 2; ++half_) {
                int m = m0 + wm * 64 + mi * 16 + (lane >> 2) + half_ * 8;
                float2 v = make_float2(acc[mi][ni][half_*2] + b0v, acc[mi][ni][half_*2+1] + b1v);
                *(float2*)(out + (size_t)m * EMB + n) = v;
            }
        }
    }
}

// V[bh][l][d] -> Vt[bh][d][l] (fp16)
__global__ void __launch_bounds__(256) transpose_v() {
    __shared__ __half t[64][66];
    const int bh = blockIdx.y, l0 = blockIdx.x * 64;
    const __half* src = g_Vf + ((size_t)bh * LSEQ + l0) * HDIM;
    __half* dst = g_Vtf + (size_t)bh * HDIM * LSEQ;
    for (int u = threadIdx.x; u < 64 * 32; u += 256) {
        int r = u >> 5, cu = u & 31;
        __half2 w = *(const __half2*)(src + (size_t)r * HDIM + cu * 2);
        t[r][cu * 2] = __low2half(w); t[r][cu * 2 + 1] = __high2half(w);
    }
    __syncthreads();
    for (int u = threadIdx.x; u < 64 * 32; u += 256) {
        int d = u >> 5, cl = u & 31;
        __half2 o = __halves2half2(t[cl * 2][d], t[cl * 2 + 1][d]);
        *(__half2*)(dst + (size_t)d * LSEQ + l0 + cl * 2) = o;
    }
}

// ---------------- fused flash attention (fp16, 1-term QK + 2-term PV) --------
// 512 thr, 16 warps x 16 q-rows = 256 q-rows per CTA.
// smem: Q@0 (32K fp16), stages@32K + (t&1)*16K {K 8K, Vt 8K}, mask@64K (2x64 f32)
#define NT (LSEQ/64)
__device__ __forceinline__ void attn_prefetch(uint32_t sb, int t,
    const __half* Kp, const __half* Vp)
{
    const int tid = threadIdx.x;
    const int s0 = t * 64;
    const uint32_t b0 = sb + 32768u + (uint32_t)(t & 1) * 16384u;
    #pragma unroll
    for (int it = 0; it < 2; ++it) {
        int u = it * 512 + tid;
        int op = u >> 9, idx = u & 511;
        int row = idx >> 3, c = idx & 7;
        uint32_t off = (uint32_t)(row * 128 + c * 16);
        const void* s = op ? (const void*)(Vp + (size_t)row * LSEQ + s0 + c * 8)
                           : (const void*)(Kp + (size_t)(s0 + row) * HDIM + c * 8);
        CPA16(b0 + (uint32_t)op * 8192u + SW128(off), s);
    }
    CPCOMMIT();
}

__global__ void __launch_bounds__(512) attn_mma(const unsigned char* __restrict__ mask) {
    extern __shared__ char sm[];
    uint32_t sb = smem_u32(sm);
    float* smb = (float*)(sm + 65536);   // [2][64]
    const int tid = threadIdx.x, lane = tid & 31, wid = tid >> 5;
    const int q0 = blockIdx.x * 256, bh = blockIdx.y, b = bh >> 4, h = bh & 15;
    const __half* Qp = g_Qf + ((size_t)bh * LSEQ + q0) * HDIM;
    const __half* Kp = g_Kf + (size_t)bh * LSEQ * HDIM;
    const __half* Vp = g_Vtf + (size_t)bh * HDIM * LSEQ;

    // Q tile (256 rows x 64 fp16) + stage 0
    #pragma unroll
    for (int it = 0; it < 4; ++it) {
        int u = it * 512 + tid;
        int row = u >> 3, c = u & 7;
        uint32_t off = (uint32_t)(row * 128 + c * 16);
        CPA16(sb + SW128(off), Qp + (size_t)row * HDIM + c * 8);
    }
    CPCOMMIT();
    attn_prefetch(sb, 0, Kp, Vp);
    if (tid < 64) smb[tid] = mask[(size_t)tid * BATCH + b] ? -1e30f : 0.0f;

    float m0s = -1e30f, m1s = -1e30f, l0s = 0.f, l1s = 0.f;
    float o[8][4] = {};

    const int arow = lane & 15;
    const uint32_t acolh = (uint32_t)((lane >> 4) * 16);
    const int brow = (lane & 7) + ((lane >> 4) << 3);
    const uint32_t bcolh = (uint32_t)(((lane >> 3) & 1) * 16);

    for (int t = 0; t < NT; ++t) {
        CPWAIT(0);
        __syncthreads();
        if (t + 1 < NT) {
            attn_prefetch(sb, t + 1, Kp, Vp);
            if (tid < 64)
                smb[((t + 1) & 1) * 64 + tid] =
                    mask[(size_t)((t + 1) * 64 + tid) * BATCH + b] ? -1e30f : 0.0f;
        }
        const float* smbt = smb + (t & 1) * 64;
        const uint32_t kb = sb + 32768u + (uint32_t)(t & 1) * 16384u;

        // S = Q K^T  (16 rows x 64 keys per warp), single fp16 pass
        float sacc[8][4] = {};
        #pragma unroll
        for (int s = 0; s < 4; ++s) {
            uint32_t qf[4];
            {
                uint32_t off = (uint32_t)((wid * 16 + arow) * 128 + s * 32) + acolh;
                LDSM4(qf[0], qf[1], qf[2], qf[3], sb + SW128(off));
            }
            uint32_t kf[8][2];
            #pragma unroll
            for (int p = 0; p < 4; ++p) {
                uint32_t off = (uint32_t)((p * 16 + brow) * 128 + s * 32) + bcolh;
                uint32_t sw = SW128(off);
                LDSM4(kf[2*p][0], kf[2*p][1], kf[2*p+1][0], kf[2*p+1][1], kb + sw);
            }
            #pragma unroll
            for (int ni = 0; ni < 8; ++ni) MMA16H(sacc[ni], qf, kf[ni]);
        }

        // mask + online softmax (rows r0 = lane>>2, r0+8)
        float mx0 = -1e30f, mx1 = -1e30f;
        #pragma unroll
        for (int ni = 0; ni < 8; ++ni) {
            float mb0 = smbt[ni * 8 + (lane & 3) * 2];
            float mb1 = smbt[ni * 8 + (lane & 3) * 2 + 1];
            sacc[ni][0] += mb0; sacc[ni][1] += mb1;
            sacc[ni][2] += mb0; sacc[ni][3] += mb1;
            mx0 = fmaxf(mx0, fmaxf(sacc[ni][0], sacc[ni][1]));
            mx1 = fmaxf(mx1, fmaxf(sacc[ni][2], sacc[ni][3]));
        }
        mx0 = fmaxf(mx0, __shfl_xor_sync(0xffffffffu, mx0, 1));
        mx0 = fmaxf(mx0, __shfl_xor_sync(0xffffffffu, mx0, 2));
        mx1 = fmaxf(mx1, __shfl_xor_sync(0xffffffffu, mx1, 1));
        mx1 = fmaxf(mx1, __shfl_xor_sync(0xffffffffu, mx1, 2));
        float mn0 = fmaxf(m0s, mx0), mn1 = fmaxf(m1s, mx1);
        float al0 = __expf(m0s - mn0), al1 = __expf(m1s - mn1);
        float su0 = 0.f, su1 = 0.f;
        #pragma unroll
        for (int ni = 0; ni < 8; ++ni) {
            sacc[ni][0] = __expf(sacc[ni][0] - mn0);
            sacc[ni][1] = __expf(sacc[ni][1] - mn0);
            sacc[ni][2] = __expf(sacc[ni][2] - mn1);
            sacc[ni][3] = __expf(sacc[ni][3] - mn1);
            su0 += sacc[ni][0] + sacc[ni][1];
            su1 += sacc[ni][2] + sacc[ni][3];
        }
        su0 += __shfl_xor_sync(0xffffffffu, su0, 1);
        su0 += __shfl_xor_sync(0xffffffffu, su0, 2);
        su1 += __shfl_xor_sync(0xffffffffu, su1, 1);
        su1 += __shfl_xor_sync(0xffffffffu, su1, 2);
        m0s = mn0; m1s = mn1;
        l0s = l0s * al0 + su0; l1s = l1s * al1 + su1;
        #pragma unroll
        for (int di = 0; di < 8; ++di) {
            o[di][0] *= al0; o[di][1] *= al0;
            o[di][2] *= al1; o[di][3] *= al1;
        }

        // O += P V : P split hi/lo in fp16 (2 passes), V single fp16
        #pragma unroll
        for (int s = 0; s < 4; ++s) {
            uint32_t ph[4], pl[4];
            packsplit_h(sacc[2*s][0],   sacc[2*s][1],   ph[0], pl[0]);
            packsplit_h(sacc[2*s][2],   sacc[2*s][3],   ph[1], pl[1]);
            packsplit_h(sacc[2*s+1][0], sacc[2*s+1][1], ph[2], pl[2]);
            packsplit_h(sacc[2*s+1][2], sacc[2*s+1][3], ph[3], pl[3]);
            uint32_t vf[8][2];
            #pragma unroll
            for (int p = 0; p < 4; ++p) {
                uint32_t off = (uint32_t)((p * 16 + brow) * 128 + s * 32) + bcolh;
                uint32_t sw = SW128(off);
                LDSM4(vf[2*p][0], vf[2*p][1], vf[2*p+1][0], vf[2*p+1][1], kb + 8192u + sw);
            }
            #pragma unroll
            for (int di = 0; di < 8; ++di) {
                MMA16H(o[di], ph, vf[di]);
                MMA16H(o[di], pl, vf[di]);
            }
        }
    }

    // normalize + write ctx (single fp16, token-major)
    float inv0 = 1.f / l0s, inv1 = 1.f / l1s;
    int r0 = q0 + wid * 16 + (lane >> 2);
    #pragma unroll
    for (int di = 0; di < 8; ++di) {
        int col = h * 64 + di * 8 + (lane & 3) * 2;
        __half2 h0 = __floats2half2_rn(o[di][0] * inv0, o[di][1] * inv0);
        *(__half2*)(g_Cf + (size_t)(r0 * BATCH + b) * EMB + col) = h0;
        __half2 h1 = __floats2half2_rn(o[di][2] * inv1, o[di][3] * inv1);
        *(__half2*)(g_Cf + (size_t)((r0 + 8) * BATCH + b) * EMB + col) = h1;
    }
}

// ---------------- launch ----------------
extern "C" void kernel_launch(void* const* d_in, const int* in_sizes, int n_in,
                              void* d_out, int out_size)
{
    const float* x     = (const float*)d_in[0];
    const float* w_in  = (const float*)d_in[1];
    const float* b_in  = (const float*)d_in[2];
    const float* w_out = (const float*)d_in[3];
    const float* b_out = (const float*)d_in[4];
    const unsigned char* mask = (const unsigned char*)d_in[5];
    float* out = (float*)d_out;

    constexpr int SMEM_PROJ = 3 * 40960;       // 3 stages x 40KB = 120KB
    constexpr int SMEM_ATTN = 65536 + 512;     // Q 32K + 2 stages x 16K + mask
    cudaFuncSetAttribute(qkv_mma,  cudaFuncAttributeMaxDynamicSharedMemorySize, SMEM_PROJ);
    cudaFuncSetAttribute(out_mma,  cudaFuncAttributeMaxDynamicSharedMemorySize, SMEM_PROJ);
    cudaFuncSetAttribute(attn_mma, cudaFuncAttributeMaxDynamicSharedMemorySize, SMEM_ATTN);

    __half *xf, *wih, *wil, *woh, *wol;
    cudaGetSymbolAddress((void**)&xf,  g_xf);
    cudaGetSymbolAddress((void**)&wih, g_wih); cudaGetSymbolAddress((void**)&wil, g_wil);
    cudaGetSymbolAddress((void**)&woh, g_woh); cudaGetSymbolAddress((void**)&wol, g_wol);

    tofp16   <<<(MTOK*EMB/4 + 255)/256, 256>>>(x,     xf,       MTOK*EMB/4);
    split_f16<<<(NQKV*EMB/4 + 255)/256, 256>>>(w_in,  wih, wil, NQKV*EMB/4);
    split_f16<<<(EMB*EMB/4  + 255)/256, 256>>>(w_out, woh, wol, EMB*EMB/4);

    qkv_mma<<<dim3(NQKV/256, MTOK/128), 512, SMEM_PROJ>>>(b_in);
    transpose_v<<<dim3(LSEQ/64, BHN), 256>>>();
    attn_mma<<<dim3(LSEQ/256, BHN), 512, SMEM_ATTN>>>(mask);
    out_mma<<<dim3(EMB/256, MTOK/128), 512, SMEM_PROJ>>>(b_out, out);
}